// round 3
// baseline (speedup 1.0000x reference)
#include <cuda_runtime.h>
#include <math.h>
#include <stdint.h>

#define B_DIM 2
#define NUM_HEADS 32
#define NUM_KV 8
#define SEQ 2048
#define DM 2048
#define HD 64

// Scratch (allocation-free: device globals)
__device__ float g_q[(size_t)B_DIM * NUM_HEADS * SEQ * HD];   // [B,H,S,D]
__device__ float g_k[(size_t)B_DIM * NUM_KV   * SEQ * HD];    // [B,KV,S,D]
__device__ float g_v[(size_t)B_DIM * NUM_KV   * SEQ * HD];    // [B,KV,S,D]
__device__ float g_ao[(size_t)B_DIM * SEQ * DM];              // [B,S,H*D]
__device__ float g_rope[(size_t)SEQ * 32 * 2];                // (cos,sin) per (s, j)

// ---------------------------------------------------------------------------
// RoPE table precompute: angle(s, j) = s * 10000^(-j/32), j in [0,32)
// ---------------------------------------------------------------------------
__global__ void rope_init()
{
    int i = blockIdx.x * blockDim.x + threadIdx.x;   // SEQ*32 threads
    int s = i >> 5, j = i & 31;
    float inv = expf(-(float)j * 0.28782313662425572f);  // ln(10000)/32
    float sv, cv;
    sincosf((float)s * inv, &sv, &cv);
    g_rope[(size_t)i * 2 + 0] = cv;
    g_rope[(size_t)i * 2 + 1] = sv;
}

// ---------------------------------------------------------------------------
// tf32 tensor-core GEMM, 128x128 CTA tile, BK=16, 4 warps (each 64x64),
// double-buffered smem, RN tf32 conversion on the store side.
// mode 0: C = A@B      mode 1: RoPE+transpose -> g_q
// mode 2: RoPE+transpose -> g_k               mode 3: transpose -> g_v
// ---------------------------------------------------------------------------
#define AS_STRIDE 20
#define BS_STRIDE 136

__device__ __forceinline__ float to_tf32(float x)
{
    float r;
    asm("cvt.rna.tf32.f32 %0, %1;" : "=f"(r) : "f"(x));
    return r;
}

__device__ __forceinline__ void mma_tf32(float* c, const uint32_t* a, const uint32_t* b)
{
    asm volatile(
        "mma.sync.aligned.m16n8k8.row.col.f32.tf32.tf32.f32 "
        "{%0,%1,%2,%3}, {%4,%5,%6,%7}, {%8,%9}, {%0,%1,%2,%3};\n"
        : "+f"(c[0]), "+f"(c[1]), "+f"(c[2]), "+f"(c[3])
        : "r"(a[0]), "r"(a[1]), "r"(a[2]), "r"(a[3]), "r"(b[0]), "r"(b[1]));
}

__global__ __launch_bounds__(128) void gemm_tc(
    const float* __restrict__ A, const float* __restrict__ Bm,
    float* __restrict__ C, int M, int N, int K, int mode)
{
    __shared__ float As[2][128 * AS_STRIDE];
    __shared__ float Bs[2][16 * BS_STRIDE];

    const int tid = threadIdx.x;
    const int wid = tid >> 5, lane = tid & 31;
    const int wm = wid & 1, wn = wid >> 1;     // 2x2 warp grid
    const int g = lane >> 2, t = lane & 3;
    const int m0 = blockIdx.y * 128, n0 = blockIdx.x * 128;

    float acc[4][8][4];
#pragma unroll
    for (int mt = 0; mt < 4; mt++)
#pragma unroll
        for (int nt = 0; nt < 8; nt++)
#pragma unroll
            for (int r = 0; r < 4; r++) acc[mt][nt][r] = 0.f;

    float4 ra[4], rb[4];

    // global loads for tile at k-offset kt
    auto LDG = [&](int kt) {
#pragma unroll
        for (int u = 0; u < 4; u++) {
            int ca = tid + 128 * u;
            int rowa = ca >> 2, kq = ca & 3;
            ra[u] = *(const float4*)&A[(size_t)(m0 + rowa) * K + kt + kq * 4];
            int rowb = ca >> 5, nq = ca & 31;
            rb[u] = *(const float4*)&Bm[(size_t)(kt + rowb) * N + n0 + nq * 4];
        }
    };
    // cvt to tf32 (RN) + store to stage s
    auto STS = [&](int s) {
#pragma unroll
        for (int u = 0; u < 4; u++) {
            int ca = tid + 128 * u;
            int rowa = ca >> 2, kq = ca & 3;
            float4 va = make_float4(to_tf32(ra[u].x), to_tf32(ra[u].y),
                                    to_tf32(ra[u].z), to_tf32(ra[u].w));
            *(float4*)&As[s][rowa * AS_STRIDE + kq * 4] = va;
            int rowb = ca >> 5, nq = ca & 31;
            float4 vb = make_float4(to_tf32(rb[u].x), to_tf32(rb[u].y),
                                    to_tf32(rb[u].z), to_tf32(rb[u].w));
            *(float4*)&Bs[s][rowb * BS_STRIDE + nq * 4] = vb;
        }
    };

    LDG(0);
    STS(0);
    const int niter = K >> 4;

    for (int i = 0; i < niter; i++) {
        __syncthreads();
        if (i + 1 < niter) LDG((i + 1) << 4);
        const int s = i & 1;

#pragma unroll
        for (int kk = 0; kk < 2; kk++) {
            const int kb = kk * 8;
            uint32_t af[4][4], bf[8][2];
#pragma unroll
            for (int mt = 0; mt < 4; mt++) {
                int r = wm * 64 + mt * 16 + g;
                af[mt][0] = __float_as_uint(As[s][r * AS_STRIDE + kb + t]);
                af[mt][1] = __float_as_uint(As[s][(r + 8) * AS_STRIDE + kb + t]);
                af[mt][2] = __float_as_uint(As[s][r * AS_STRIDE + kb + t + 4]);
                af[mt][3] = __float_as_uint(As[s][(r + 8) * AS_STRIDE + kb + t + 4]);
            }
#pragma unroll
            for (int nt = 0; nt < 8; nt++) {
                int c = wn * 64 + nt * 8 + g;
                bf[nt][0] = __float_as_uint(Bs[s][(kb + t) * BS_STRIDE + c]);
                bf[nt][1] = __float_as_uint(Bs[s][(kb + t + 4) * BS_STRIDE + c]);
            }
#pragma unroll
            for (int mt = 0; mt < 4; mt++)
#pragma unroll
                for (int nt = 0; nt < 8; nt++)
                    mma_tf32(acc[mt][nt], af[mt], bf[nt]);
        }
        if (i + 1 < niter) {
            __syncthreads();
            STS((i + 1) & 1);
        }
    }

    // ---------------- epilogue ----------------
    if (mode == 0) {
#pragma unroll
        for (int mt = 0; mt < 4; mt++) {
            int row = m0 + wm * 64 + mt * 16 + g;
#pragma unroll
            for (int nt = 0; nt < 8; nt++) {
                int col = n0 + wn * 64 + nt * 8 + t * 2;
                *(float2*)&C[(size_t)row * N + col] =
                    make_float2(acc[mt][nt][0], acc[mt][nt][1]);
                *(float2*)&C[(size_t)(row + 8) * N + col] =
                    make_float2(acc[mt][nt][2], acc[mt][nt][3]);
            }
        }
        return;
    }

    // RoPE (+optional) transpose epilogue
#pragma unroll
    for (int mt = 0; mt < 4; mt++) {
#pragma unroll
        for (int half = 0; half < 2; half++) {
            int row = m0 + wm * 64 + mt * 16 + g + half * 8;
            int b = row >> 11;
            int sp = row & (SEQ - 1);
#pragma unroll
            for (int nt = 0; nt < 8; nt++) {
                int col = n0 + wn * 64 + nt * 8 + t * 2;   // even
                int h = col >> 6;
                int d0 = col & 63;
                float v0 = acc[mt][nt][half * 2 + 0];
                float v1 = acc[mt][nt][half * 2 + 1];
                float o0, o1;
                if (mode == 3) {
                    o0 = v0; o1 = v1;
                } else {
                    int j0 = d0 & 31, j1 = (d0 + 1) & 31;
                    float2 cs0 = *(const float2*)&g_rope[((size_t)sp * 32 + j0) * 2];
                    float2 cs1 = *(const float2*)&g_rope[((size_t)sp * 32 + j1) * 2];
                    o0 = v0 * cs0.x - v1 * cs0.y;
                    o1 = v1 * cs1.x + v0 * cs1.y;
                }
                float* dst;
                if (mode == 1)
                    dst = &g_q[(((size_t)b * NUM_HEADS + h) * SEQ + sp) * HD + d0];
                else if (mode == 2)
                    dst = &g_k[(((size_t)b * NUM_KV + h) * SEQ + sp) * HD + d0];
                else
                    dst = &g_v[(((size_t)b * NUM_KV + h) * SEQ + sp) * HD + d0];
                *(float2*)dst = make_float2(o0, o1);
            }
        }
    }
}

// ---------------------------------------------------------------------------
// Flash attention: 64x64 tiles, fp32, online softmax. P aliased onto K smem
// (48KB total -> 4 CTAs/SM with launch_bounds(256,4)).
// ---------------------------------------------------------------------------
__global__ __launch_bounds__(256, 4) void flash_attn()
{
    extern __shared__ float sm[];
    float* q_s = sm;             // [64][64]  d-major
    float* k_s = sm + 4096;      // [64][64]  d-major; reused as P [64][64] row-major
    float* v_s = sm + 8192;      // [64][64]  key-major

    const int tid = threadIdx.x;
    const int ty = tid >> 4;
    const int tx = tid & 15;
    const int qs = blockIdx.x * 64;
    const int h  = blockIdx.y;
    const int b  = blockIdx.z;
    const int kvh = h >> 2;

    const float* qg = &g_q[(((size_t)b * NUM_HEADS + h) * SEQ + qs) * HD];
    const float* kg = &g_k[(((size_t)b * NUM_KV + kvh) * SEQ) * HD];
    const float* vg = &g_v[(((size_t)b * NUM_KV + kvh) * SEQ) * HD];

    // Load Q tile, transposed to d-major
    {
        int r = tid >> 2;
        int c = (tid & 3) * 16;
#pragma unroll
        for (int u = 0; u < 4; u++) {
            float4 v4 = *(const float4*)&qg[r * 64 + c + u * 4];
            q_s[(c + u * 4 + 0) * 64 + r] = v4.x;
            q_s[(c + u * 4 + 1) * 64 + r] = v4.y;
            q_s[(c + u * 4 + 2) * 64 + r] = v4.z;
            q_s[(c + u * 4 + 3) * 64 + r] = v4.w;
        }
    }

    float m_i[4], l_i[4], acc[4][4];
#pragma unroll
    for (int i = 0; i < 4; i++) {
        m_i[i] = -1e30f;
        l_i[i] = 0.f;
#pragma unroll
        for (int j = 0; j < 4; j++) acc[i][j] = 0.f;
    }

    const float scale = 0.125f;

    for (int kt = 0; kt <= qs; kt += 64) {
        __syncthreads();  // prior PV reads (v_s, P=k_s) done; q_s visible on iter 0
        {
            int r = tid >> 2;
            int c = (tid & 3) * 16;
#pragma unroll
            for (int u = 0; u < 4; u++) {
                float4 kv4 = *(const float4*)&kg[(size_t)(kt + r) * 64 + c + u * 4];
                k_s[(c + u * 4 + 0) * 64 + r] = kv4.x;
                k_s[(c + u * 4 + 1) * 64 + r] = kv4.y;
                k_s[(c + u * 4 + 2) * 64 + r] = kv4.z;
                k_s[(c + u * 4 + 3) * 64 + r] = kv4.w;
                float4 vv4 = *(const float4*)&vg[(size_t)(kt + r) * 64 + c + u * 4];
                *(float4*)&v_s[r * 64 + c + u * 4] = vv4;
            }
        }
        __syncthreads();

        // S = Q @ K^T
        float sreg[4][4];
#pragma unroll
        for (int i = 0; i < 4; i++)
#pragma unroll
            for (int j = 0; j < 4; j++) sreg[i][j] = 0.f;

#pragma unroll 16
        for (int kd = 0; kd < 64; kd++) {
            float4 qf = *(float4*)&q_s[kd * 64 + ty * 4];
            float4 kf = *(float4*)&k_s[kd * 64 + tx * 4];
            float qa[4] = {qf.x, qf.y, qf.z, qf.w};
            float ka[4] = {kf.x, kf.y, kf.z, kf.w};
#pragma unroll
            for (int i = 0; i < 4; i++)
#pragma unroll
                for (int j = 0; j < 4; j++)
                    sreg[i][j] = fmaf(qa[i], ka[j], sreg[i][j]);
        }

        __syncthreads();  // all S reads of k_s done before P overwrites it

        // scale + causal mask
#pragma unroll
        for (int i = 0; i < 4; i++) {
            int row = qs + ty * 4 + i;
#pragma unroll
            for (int j = 0; j < 4; j++) {
                int col = kt + tx * 4 + j;
                float v = sreg[i][j] * scale;
                sreg[i][j] = (col > row) ? -1e30f : v;
            }
        }

        // online softmax, write P into k_s region
#pragma unroll
        for (int i = 0; i < 4; i++) {
            float mx = fmaxf(fmaxf(sreg[i][0], sreg[i][1]),
                             fmaxf(sreg[i][2], sreg[i][3]));
#pragma unroll
            for (int off = 8; off >= 1; off >>= 1)
                mx = fmaxf(mx, __shfl_xor_sync(0xffffffffu, mx, off));
            float mnew = fmaxf(m_i[i], mx);
            float alpha = __expf(m_i[i] - mnew);
            float ps = 0.f;
#pragma unroll
            for (int j = 0; j < 4; j++) {
                float p = __expf(sreg[i][j] - mnew);
                sreg[i][j] = p;
                ps += p;
            }
#pragma unroll
            for (int off = 8; off >= 1; off >>= 1)
                ps += __shfl_xor_sync(0xffffffffu, ps, off);
            l_i[i] = l_i[i] * alpha + ps;
            m_i[i] = mnew;
#pragma unroll
            for (int j = 0; j < 4; j++) acc[i][j] *= alpha;
            *(float4*)&k_s[(ty * 4 + i) * 64 + tx * 4] =
                make_float4(sreg[i][0], sreg[i][1], sreg[i][2], sreg[i][3]);
        }
        __syncthreads();

        // O += P @ V   (P lives in k_s)
#pragma unroll 8
        for (int kk = 0; kk < 64; kk++) {
            float4 vf = *(float4*)&v_s[kk * 64 + tx * 4];
#pragma unroll
            for (int i = 0; i < 4; i++) {
                float p = k_s[(ty * 4 + i) * 64 + kk];
                acc[i][0] = fmaf(p, vf.x, acc[i][0]);
                acc[i][1] = fmaf(p, vf.y, acc[i][1]);
                acc[i][2] = fmaf(p, vf.z, acc[i][2]);
                acc[i][3] = fmaf(p, vf.w, acc[i][3]);
            }
        }
    }

    float* og = &g_ao[((size_t)b * SEQ + qs) * DM + h * HD];
#pragma unroll
    for (int i = 0; i < 4; i++) {
        float inv = 1.f / l_i[i];
        float4 o = make_float4(acc[i][0] * inv, acc[i][1] * inv,
                               acc[i][2] * inv, acc[i][3] * inv);
        *(float4*)&og[(size_t)(ty * 4 + i) * DM + tx * 4] = o;
    }
}

// ---------------------------------------------------------------------------

extern "C" void kernel_launch(void* const* d_in, const int* in_sizes, int n_in,
                              void* d_out, int out_size)
{
    const float* x  = (const float*)d_in[0];
    const float* Wq = (const float*)d_in[2];
    const float* Wk = (const float*)d_in[3];
    const float* Wv = (const float*)d_in[4];
    const float* Wo = (const float*)d_in[5];
    float* out = (float*)d_out;

    const int M = B_DIM * SEQ;  // 4096

    cudaFuncSetAttribute(flash_attn, cudaFuncAttributeMaxDynamicSharedMemorySize,
                         48 * 1024);

    rope_init<<<(SEQ * 32) / 256, 256>>>();

    gemm_tc<<<dim3(DM / 128, M / 128), 128>>>(x, Wq, nullptr, M, DM, DM, 1);
    gemm_tc<<<dim3((NUM_KV * HD) / 128, M / 128), 128>>>(x, Wk, nullptr, M, NUM_KV * HD, DM, 2);
    gemm_tc<<<dim3((NUM_KV * HD) / 128, M / 128), 128>>>(x, Wv, nullptr, M, NUM_KV * HD, DM, 3);

    flash_attn<<<dim3(SEQ / 64, NUM_HEADS, B_DIM), 256, 48 * 1024>>>();

    void* aoPtr = nullptr;
    cudaGetSymbolAddress(&aoPtr, g_ao);
    gemm_tc<<<dim3(DM / 128, M / 128), 128>>>((const float*)aoPtr, Wo, out, M, DM, DM, 0);
}

// round 4
// speedup vs baseline: 4.3773x; 4.3773x over previous
#include <cuda_runtime.h>
#include <cuda_fp16.h>
#include <math.h>
#include <stdint.h>

#define B_DIM 2
#define NUM_HEADS 32
#define NUM_KV 8
#define SEQ 2048
#define DM 2048
#define HD 64
#define MTOT (B_DIM * SEQ)

// fp16 scratch (allocation-free device globals)
__device__ __half g_xh[(size_t)MTOT * DM];
__device__ __half g_wq[(size_t)DM * DM];
__device__ __half g_wk[(size_t)DM * 512];
__device__ __half g_wv[(size_t)DM * 512];
__device__ __half g_wo[(size_t)DM * DM];
__device__ __half g_q[(size_t)B_DIM * NUM_HEADS * SEQ * HD];
__device__ __half g_k[(size_t)B_DIM * NUM_KV * SEQ * HD];
__device__ __half g_v[(size_t)B_DIM * NUM_KV * SEQ * HD];
__device__ __half g_ao[(size_t)MTOT * DM];
__device__ float  g_rope[SEQ * 32 * 2];

// ---------------------------------------------------------------------------
__global__ void rope_init()
{
    int i = blockIdx.x * blockDim.x + threadIdx.x;
    int s = i >> 5, j = i & 31;
    float inv = expf(-(float)j * 0.28782313662425572f);
    float sv, cv;
    sincosf((float)s * inv, &sv, &cv);
    g_rope[(size_t)i * 2 + 0] = cv;
    g_rope[(size_t)i * 2 + 1] = sv;
}

__global__ void f2h(const float4* __restrict__ src, __half* __restrict__ dst, int n4)
{
    int i = blockIdx.x * blockDim.x + threadIdx.x;
    if (i < n4) {
        float4 v = src[i];
        __half2* d = (__half2*)(dst + (size_t)i * 4);
        d[0] = __floats2half2_rn(v.x, v.y);
        d[1] = __floats2half2_rn(v.z, v.w);
    }
}

// ---------------------------------------------------------------------------
// Helpers
// ---------------------------------------------------------------------------
__device__ __forceinline__ uint32_t smem_u32(const void* p)
{
    return (uint32_t)__cvta_generic_to_shared(p);
}
__device__ __forceinline__ void ldmx4(uint32_t* r, uint32_t a)
{
    asm volatile("ldmatrix.sync.aligned.m8n8.x4.shared.b16 {%0,%1,%2,%3}, [%4];"
                 : "=r"(r[0]), "=r"(r[1]), "=r"(r[2]), "=r"(r[3]) : "r"(a));
}
__device__ __forceinline__ void ldmx4t(uint32_t* r, uint32_t a)
{
    asm volatile("ldmatrix.sync.aligned.m8n8.x4.trans.shared.b16 {%0,%1,%2,%3}, [%4];"
                 : "=r"(r[0]), "=r"(r[1]), "=r"(r[2]), "=r"(r[3]) : "r"(a));
}
__device__ __forceinline__ void mma_f16(float* c, const uint32_t* a, const uint32_t* b)
{
    asm volatile(
        "mma.sync.aligned.m16n8k16.row.col.f32.f16.f16.f32 "
        "{%0,%1,%2,%3}, {%4,%5,%6,%7}, {%8,%9}, {%0,%1,%2,%3};"
        : "+f"(c[0]), "+f"(c[1]), "+f"(c[2]), "+f"(c[3])
        : "r"(a[0]), "r"(a[1]), "r"(a[2]), "r"(a[3]), "r"(b[0]), "r"(b[1]));
}
__device__ __forceinline__ void cp16(uint32_t saddr, const void* g)
{
    asm volatile("cp.async.cg.shared.global [%0], [%1], 16;" :: "r"(saddr), "l"(g));
}
#define CP_COMMIT() asm volatile("cp.async.commit_group;")
#define CP_WAIT(n)  asm volatile("cp.async.wait_group %0;" :: "n"(n))

__device__ __forceinline__ float ex2(float x)
{
    float r;
    asm("ex2.approx.ftz.f32 %0, %1;" : "=f"(r) : "f"(x));
    return r;
}
__device__ __forceinline__ uint32_t packh2(float lo, float hi)
{
    __half2 h = __floats2half2_rn(lo, hi);
    return *reinterpret_cast<uint32_t*>(&h);
}

// ---------------------------------------------------------------------------
// fp16 GEMM, CTA 128x128, BK=32, 8 warps (4m x 2n, warp tile 32x64),
// 4-stage cp.async pipeline.  mode 0: C fp32 (Wo)   mode 1: RoPE->g_q
// mode 2: fused KV (n<512: RoPE->g_k, else ->g_v)
// ---------------------------------------------------------------------------
#define A_ST 40
#define B_ST 136
#define A_SZ (128 * A_ST)
#define B_SZ (32 * B_ST)
#define GSMEM (4 * (A_SZ + B_SZ) * 2)

__global__ __launch_bounds__(256, 2) void gemm_f16(
    const __half* __restrict__ A, const __half* __restrict__ B0,
    const __half* __restrict__ B1, float* __restrict__ C,
    int Nb, int K, int mode)
{
    extern __shared__ __half smem[];
    __half* As = smem;
    __half* Bs = smem + 4 * A_SZ;

    const int tid = threadIdx.x, lane = tid & 31, wid = tid >> 5;
    const int wm = wid & 3, wn = wid >> 2;
    const int g = lane >> 2, t = lane & 3;
    const int m0 = blockIdx.y * 128;
    int n0 = blockIdx.x * 128;
    const __half* Bm = B0;
    int vmode = mode;
    if (mode == 2) {
        if (n0 >= 512) { Bm = B1; n0 -= 512; vmode = 3; }
    }

    const uint32_t sA = smem_u32(As), sB = smem_u32(Bs);

    float acc[2][8][4];
#pragma unroll
    for (int mf = 0; mf < 2; mf++)
#pragma unroll
        for (int nt = 0; nt < 8; nt++)
#pragma unroll
            for (int r = 0; r < 4; r++) acc[mf][nt][r] = 0.f;

    auto issue = [&](int it) {
        int kt = it * 32, st = it & 3;
#pragma unroll
        for (int u = 0; u < 2; u++) {
            int c = tid + 256 * u;
            int r = c >> 2, q = c & 3;
            cp16(sA + (st * A_SZ + r * A_ST + q * 8) * 2,
                 &A[(size_t)(m0 + r) * K + kt + q * 8]);
        }
#pragma unroll
        for (int u = 0; u < 2; u++) {
            int c = tid + 256 * u;
            int r = c >> 4, q = c & 15;
            cp16(sB + (st * B_SZ + r * B_ST + q * 8) * 2,
                 &Bm[(size_t)(kt + r) * Nb + n0 + q * 8]);
        }
    };

    const int niter = K >> 5;
    issue(0); CP_COMMIT();
    issue(1); CP_COMMIT();
    issue(2); CP_COMMIT();

    for (int i = 0; i < niter; i++) {
        CP_WAIT(2);
        __syncthreads();
        const int st = i & 3;
        const uint32_t ab = sA + st * A_SZ * 2;
        const uint32_t bb = sB + st * B_SZ * 2;
#pragma unroll
        for (int ks = 0; ks < 2; ks++) {
            const int kb = ks * 16;
            uint32_t af[2][4], bf[8][2];
#pragma unroll
            for (int mf = 0; mf < 2; mf++)
                ldmx4(af[mf], ab + ((wm * 32 + mf * 16 + (lane & 15)) * A_ST +
                                    kb + (lane >> 4) * 8) * 2);
#pragma unroll
            for (int p = 0; p < 4; p++) {
                uint32_t r[4];
                ldmx4t(r, bb + ((kb + (lane & 15)) * B_ST +
                                wn * 64 + p * 16 + (lane >> 4) * 8) * 2);
                bf[2 * p][0] = r[0]; bf[2 * p][1] = r[1];
                bf[2 * p + 1][0] = r[2]; bf[2 * p + 1][1] = r[3];
            }
#pragma unroll
            for (int mf = 0; mf < 2; mf++)
#pragma unroll
                for (int nt = 0; nt < 8; nt++)
                    mma_f16(acc[mf][nt], af[mf], bf[nt]);
        }
        if (i + 3 < niter) issue(i + 3);
        CP_COMMIT();
    }

    // ---------------- epilogue ----------------
    if (mode == 0) {
#pragma unroll
        for (int mf = 0; mf < 2; mf++) {
            int r = m0 + wm * 32 + mf * 16 + g;
#pragma unroll
            for (int nt = 0; nt < 8; nt++) {
                int col = n0 + wn * 64 + nt * 8 + t * 2;
                *(float2*)&C[(size_t)r * DM + col] =
                    make_float2(acc[mf][nt][0], acc[mf][nt][1]);
                *(float2*)&C[(size_t)(r + 8) * DM + col] =
                    make_float2(acc[mf][nt][2], acc[mf][nt][3]);
            }
        }
        return;
    }

#pragma unroll
    for (int mf = 0; mf < 2; mf++) {
#pragma unroll
        for (int hh = 0; hh < 2; hh++) {
            int row = m0 + wm * 32 + mf * 16 + g + hh * 8;
            int b = row >> 11;
            int s = row & (SEQ - 1);
#pragma unroll
            for (int nt = 0; nt < 8; nt++) {
                int col = n0 + wn * 64 + nt * 8 + t * 2;   // even
                float v0 = acc[mf][nt][hh * 2 + 0];
                float v1 = acc[mf][nt][hh * 2 + 1];
                int d0 = col & 63;
                if (vmode != 3) {
                    int j0 = d0 & 31, j1 = (d0 + 1) & 31;
                    float2 cs0 = *(const float2*)&g_rope[((size_t)s * 32 + j0) * 2];
                    float2 cs1 = *(const float2*)&g_rope[((size_t)s * 32 + j1) * 2];
                    float o0 = v0 * cs0.x - v1 * cs0.y;
                    float o1 = v1 * cs1.x + v0 * cs1.y;
                    v0 = o0; v1 = o1;
                }
                int h = col >> 6;
                __half2 hv = __floats2half2_rn(v0, v1);
                if (vmode == 1)
                    *(__half2*)&g_q[(((size_t)b * NUM_HEADS + h) * SEQ + s) * HD + d0] = hv;
                else if (vmode == 2)
                    *(__half2*)&g_k[(((size_t)b * NUM_KV + h) * SEQ + s) * HD + d0] = hv;
                else
                    *(__half2*)&g_v[(((size_t)b * NUM_KV + h) * SEQ + s) * HD + d0] = hv;
            }
        }
    }
}

// ---------------------------------------------------------------------------
// fp16 mma flash attention. Q tile 128 (8 warps x 16 rows), KV tile 64,
// double-buffered cp.async K/V. Softmax fp32 on fragments.
// ---------------------------------------------------------------------------
#define FSTR 72

__global__ __launch_bounds__(256) void fa_f16()
{
    extern __shared__ __half sm[];
    __half* q_s = sm;                        // [128][72]
    __half* k_s = sm + 128 * FSTR;           // [2][64][72]
    __half* v_s = sm + 128 * FSTR + 2 * 64 * FSTR;

    const int tid = threadIdx.x, lane = tid & 31, w = tid >> 5;
    const int g = lane >> 2, t = lane & 3;
    const int qs = blockIdx.x * 128;
    const int h = blockIdx.y, b = blockIdx.z;
    const int kvh = h >> 2;

    const __half* qg = &g_q[(((size_t)b * NUM_HEADS + h) * SEQ + qs) * HD];
    const __half* kg = &g_k[(((size_t)b * NUM_KV + kvh) * SEQ) * HD];
    const __half* vg = &g_v[(((size_t)b * NUM_KV + kvh) * SEQ) * HD];

    const uint32_t sq = smem_u32(q_s), sk = smem_u32(k_s), sv = smem_u32(v_s);

    // group 0: Q tile + KV tile 0
#pragma unroll
    for (int u = 0; u < 4; u++) {
        int c = tid + 256 * u;
        int r = c >> 3, q = c & 7;
        cp16(sq + (r * FSTR + q * 8) * 2, qg + (size_t)r * 64 + q * 8);
    }
    auto issue_kv = [&](int it) {
        int st = it & 1, koff = it * 64;
#pragma unroll
        for (int u = 0; u < 2; u++) {
            int c = tid + 256 * u;
            int r = c >> 3, q = c & 7;
            cp16(sk + (st * 64 * FSTR + r * FSTR + q * 8) * 2,
                 kg + (size_t)(koff + r) * 64 + q * 8);
            cp16(sv + (st * 64 * FSTR + r * FSTR + q * 8) * 2,
                 vg + (size_t)(koff + r) * 64 + q * 8);
        }
    };
    const int ntiles = qs / 64 + 2;
    issue_kv(0); CP_COMMIT();
    if (ntiles > 1) issue_kv(1);
    CP_COMMIT();

    float o[8][4];
#pragma unroll
    for (int p = 0; p < 8; p++)
#pragma unroll
        for (int r = 0; r < 4; r++) o[p][r] = 0.f;
    float m0r = -1e30f, m1r = -1e30f, l0 = 0.f, l1 = 0.f;
    uint32_t qf[4][4];

    const float SC = 0.125f * 1.4426950408889634f;

    for (int it = 0; it < ntiles; it++) {
        CP_WAIT(1);
        __syncthreads();
        if (it == 0) {
#pragma unroll
            for (int kc = 0; kc < 4; kc++)
                ldmx4(qf[kc], sq + ((w * 16 + (lane & 15)) * FSTR +
                                    kc * 16 + (lane >> 4) * 8) * 2);
        }
        const uint32_t kb = sk + ((it & 1) * 64 * FSTR) * 2;
        const uint32_t vb = sv + ((it & 1) * 64 * FSTR) * 2;

        // S = Q @ K^T
        float s[8][4];
#pragma unroll
        for (int p = 0; p < 8; p++)
#pragma unroll
            for (int r = 0; r < 4; r++) s[p][r] = 0.f;
#pragma unroll
        for (int kc = 0; kc < 4; kc++) {
#pragma unroll
            for (int p = 0; p < 4; p++) {
                uint32_t r[4];
                // key row = p*16 + (lane&7) + ((lane>>4)&1)*8 ; col = kc*16 + ((lane>>3)&1)*8
                ldmx4(r, kb + ((p * 16 + (lane & 7) + ((lane >> 4) & 1) * 8) * FSTR +
                               kc * 16 + ((lane >> 3) & 1) * 8) * 2);
                mma_f16(s[2 * p], qf[kc], r);
                mma_f16(s[2 * p + 1], qf[kc], r + 2);
            }
        }

        // scale (+causal mask on boundary tiles)
        const int kt = it * 64;
        const int rowg = qs + w * 16 + g;
#pragma unroll
        for (int p = 0; p < 8; p++)
#pragma unroll
            for (int r = 0; r < 4; r++) s[p][r] *= SC;
        if (kt + 63 > qs + w * 16) {
#pragma unroll
            for (int p = 0; p < 8; p++) {
                int col = kt + p * 8 + 2 * t;
                if (col > rowg)     s[p][0] = -1e30f;
                if (col + 1 > rowg) s[p][1] = -1e30f;
                if (col > rowg + 8)     s[p][2] = -1e30f;
                if (col + 1 > rowg + 8) s[p][3] = -1e30f;
            }
        }

        // online softmax (rows g and g+8), quad reductions
        float mx0 = -1e30f, mx1 = -1e30f;
#pragma unroll
        for (int p = 0; p < 8; p++) {
            mx0 = fmaxf(mx0, fmaxf(s[p][0], s[p][1]));
            mx1 = fmaxf(mx1, fmaxf(s[p][2], s[p][3]));
        }
        mx0 = fmaxf(mx0, __shfl_xor_sync(0xffffffffu, mx0, 1));
        mx0 = fmaxf(mx0, __shfl_xor_sync(0xffffffffu, mx0, 2));
        mx1 = fmaxf(mx1, __shfl_xor_sync(0xffffffffu, mx1, 1));
        mx1 = fmaxf(mx1, __shfl_xor_sync(0xffffffffu, mx1, 2));
        float mn0 = fmaxf(m0r, mx0), mn1 = fmaxf(m1r, mx1);
        float a0 = ex2(m0r - mn0), a1 = ex2(m1r - mn1);
        m0r = mn0; m1r = mn1;

        float ps0 = 0.f, ps1 = 0.f;
        uint32_t pf[4][4];
#pragma unroll
        for (int p = 0; p < 8; p++) {
            float p0 = ex2(s[p][0] - mn0);
            float p1 = ex2(s[p][1] - mn0);
            float p2 = ex2(s[p][2] - mn1);
            float p3 = ex2(s[p][3] - mn1);
            ps0 += p0 + p1;
            ps1 += p2 + p3;
            int kc = p >> 1;
            if ((p & 1) == 0) {
                pf[kc][0] = packh2(p0, p1);
                pf[kc][1] = packh2(p2, p3);
            } else {
                pf[kc][2] = packh2(p0, p1);
                pf[kc][3] = packh2(p2, p3);
            }
        }
        ps0 += __shfl_xor_sync(0xffffffffu, ps0, 1);
        ps0 += __shfl_xor_sync(0xffffffffu, ps0, 2);
        ps1 += __shfl_xor_sync(0xffffffffu, ps1, 1);
        ps1 += __shfl_xor_sync(0xffffffffu, ps1, 2);
        l0 = l0 * a0 + ps0;
        l1 = l1 * a1 + ps1;
#pragma unroll
        for (int p = 0; p < 8; p++) {
            o[p][0] *= a0; o[p][1] *= a0;
            o[p][2] *= a1; o[p][3] *= a1;
        }

        // O += P @ V
#pragma unroll
        for (int kc = 0; kc < 4; kc++) {
#pragma unroll
            for (int p = 0; p < 4; p++) {
                uint32_t r[4];
                ldmx4t(r, vb + ((kc * 16 + (lane & 15)) * FSTR +
                                p * 16 + ((lane >> 4) & 1) * 8) * 2);
                mma_f16(o[2 * p], pf[kc], r);
                mma_f16(o[2 * p + 1], pf[kc], r + 2);
            }
        }

        __syncthreads();
        if (it + 2 < ntiles) issue_kv(it + 2);
        CP_COMMIT();
    }

    // epilogue
    float inv0 = 1.f / l0, inv1 = 1.f / l1;
    __half* og = &g_ao[((size_t)(b * SEQ + qs + w * 16)) * DM + h * HD];
#pragma unroll
    for (int p = 0; p < 8; p++) {
        int col = p * 8 + 2 * t;
        *(__half2*)&og[(size_t)g * DM + col] =
            __floats2half2_rn(o[p][0] * inv0, o[p][1] * inv0);
        *(__half2*)&og[(size_t)(g + 8) * DM + col] =
            __floats2half2_rn(o[p][2] * inv1, o[p][3] * inv1);
    }
}

// ---------------------------------------------------------------------------

extern "C" void kernel_launch(void* const* d_in, const int* in_sizes, int n_in,
                              void* d_out, int out_size)
{
    const float* x  = (const float*)d_in[0];
    const float* Wq = (const float*)d_in[2];
    const float* Wk = (const float*)d_in[3];
    const float* Wv = (const float*)d_in[4];
    const float* Wo = (const float*)d_in[5];
    float* out = (float*)d_out;

    void *xh, *wq, *wk, *wv, *wo, *ao;
    cudaGetSymbolAddress(&xh, g_xh);
    cudaGetSymbolAddress(&wq, g_wq);
    cudaGetSymbolAddress(&wk, g_wk);
    cudaGetSymbolAddress(&wv, g_wv);
    cudaGetSymbolAddress(&wo, g_wo);
    cudaGetSymbolAddress(&ao, g_ao);

    static bool attr_done = false;
    if (!attr_done) {
        cudaFuncSetAttribute(gemm_f16, cudaFuncAttributeMaxDynamicSharedMemorySize, GSMEM);
        cudaFuncSetAttribute(fa_f16, cudaFuncAttributeMaxDynamicSharedMemorySize,
                             (128 + 4 * 64) * FSTR * 2);
        attr_done = true;
    }

    // fp32 -> fp16 conversions
    f2h<<<(MTOT * DM / 4 + 255) / 256, 256>>>((const float4*)x, (__half*)xh, MTOT * DM / 4);
    f2h<<<(DM * DM / 4 + 255) / 256, 256>>>((const float4*)Wq, (__half*)wq, DM * DM / 4);
    f2h<<<(DM * 512 / 4 + 255) / 256, 256>>>((const float4*)Wk, (__half*)wk, DM * 512 / 4);
    f2h<<<(DM * 512 / 4 + 255) / 256, 256>>>((const float4*)Wv, (__half*)wv, DM * 512 / 4);
    f2h<<<(DM * DM / 4 + 255) / 256, 256>>>((const float4*)Wo, (__half*)wo, DM * DM / 4);

    rope_init<<<(SEQ * 32) / 256, 256>>>();

    // Q projection (RoPE fused)
    gemm_f16<<<dim3(DM / 128, MTOT / 128), 256, GSMEM>>>(
        (const __half*)xh, (const __half*)wq, nullptr, nullptr, DM, DM, 1);
    // fused K+V projections (RoPE on K)
    gemm_f16<<<dim3(1024 / 128, MTOT / 128), 256, GSMEM>>>(
        (const __half*)xh, (const __half*)wk, (const __half*)wv, nullptr, 512, DM, 2);

    // flash attention
    fa_f16<<<dim3(SEQ / 128, NUM_HEADS, B_DIM), 256, (128 + 4 * 64) * FSTR * 2>>>();

    // output projection
    gemm_f16<<<dim3(DM / 128, MTOT / 128), 256, GSMEM>>>(
        (const __half*)ao, (const __half*)wo, nullptr, out, DM, DM, 0);
}

// round 6
// speedup vs baseline: 4.5758x; 1.0454x over previous
#include <cuda_runtime.h>
#include <cuda_fp16.h>
#include <math.h>
#include <stdint.h>

#define B_DIM 2
#define NUM_HEADS 32
#define NUM_KV 8
#define SEQ 2048
#define DM 2048
#define HD 64
#define MTOT (B_DIM * SEQ)

// fp16 scratch (allocation-free device globals)
__device__ __half g_xh[(size_t)MTOT * DM];
__device__ __half g_wq[(size_t)DM * DM];
__device__ __half g_wk[(size_t)DM * 512];
__device__ __half g_wv[(size_t)DM * 512];
__device__ __half g_wo[(size_t)DM * DM];
__device__ __half g_q[(size_t)B_DIM * NUM_HEADS * SEQ * HD];
__device__ __half g_k[(size_t)B_DIM * NUM_KV * SEQ * HD];
__device__ __half g_v[(size_t)B_DIM * NUM_KV * SEQ * HD];
__device__ __half g_ao[(size_t)MTOT * DM];
__device__ float  g_rope[SEQ * 32 * 2];

// softmax scale folded into Q at projection time: 1/sqrt(64) * log2(e)
#define QSCALE 0.1803368801111204f

// ---------------------------------------------------------------------------
__global__ void rope_init()
{
    int i = blockIdx.x * blockDim.x + threadIdx.x;
    int s = i >> 5, j = i & 31;
    float inv = expf(-(float)j * 0.28782313662425572f);
    float sv, cv;
    sincosf((float)s * inv, &sv, &cv);
    g_rope[(size_t)i * 2 + 0] = cv;
    g_rope[(size_t)i * 2 + 1] = sv;
}

__global__ void f2h(const float4* __restrict__ src, __half* __restrict__ dst, int n4)
{
    int i = blockIdx.x * blockDim.x + threadIdx.x;
    if (i < n4) {
        float4 v = src[i];
        __half2* d = (__half2*)(dst + (size_t)i * 4);
        d[0] = __floats2half2_rn(v.x, v.y);
        d[1] = __floats2half2_rn(v.z, v.w);
    }
}

// ---------------------------------------------------------------------------
// Helpers
// ---------------------------------------------------------------------------
__device__ __forceinline__ uint32_t smem_u32(const void* p)
{
    return (uint32_t)__cvta_generic_to_shared(p);
}
__device__ __forceinline__ void ldmx4(uint32_t* r, uint32_t a)
{
    asm volatile("ldmatrix.sync.aligned.m8n8.x4.shared.b16 {%0,%1,%2,%3}, [%4];"
                 : "=r"(r[0]), "=r"(r[1]), "=r"(r[2]), "=r"(r[3]) : "r"(a));
}
__device__ __forceinline__ void ldmx4t(uint32_t* r, uint32_t a)
{
    asm volatile("ldmatrix.sync.aligned.m8n8.x4.trans.shared.b16 {%0,%1,%2,%3}, [%4];"
                 : "=r"(r[0]), "=r"(r[1]), "=r"(r[2]), "=r"(r[3]) : "r"(a));
}
__device__ __forceinline__ void mma_f16(float* c, const uint32_t* a, const uint32_t* b)
{
    asm volatile(
        "mma.sync.aligned.m16n8k16.row.col.f32.f16.f16.f32 "
        "{%0,%1,%2,%3}, {%4,%5,%6,%7}, {%8,%9}, {%0,%1,%2,%3};"
        : "+f"(c[0]), "+f"(c[1]), "+f"(c[2]), "+f"(c[3])
        : "r"(a[0]), "r"(a[1]), "r"(a[2]), "r"(a[3]), "r"(b[0]), "r"(b[1]));
}
__device__ __forceinline__ void cp16(uint32_t saddr, const void* g)
{
    asm volatile("cp.async.cg.shared.global [%0], [%1], 16;" :: "r"(saddr), "l"(g));
}
#define CP_COMMIT() asm volatile("cp.async.commit_group;")
#define CP_WAIT(n)  asm volatile("cp.async.wait_group %0;" :: "n"(n))

__device__ __forceinline__ float ex2(float x)
{
    float r;
    asm("ex2.approx.ftz.f32 %0, %1;" : "=f"(r) : "f"(x));
    return r;
}
__device__ __forceinline__ uint32_t packh2(float lo, float hi)
{
    __half2 h = __floats2half2_rn(lo, hi);
    return *reinterpret_cast<uint32_t*>(&h);
}

// ---------------------------------------------------------------------------
// fp16 GEMM, CTA 128x128, BK=32, 8 warps (4m x 2n, warp tile 32x64),
// 4-stage cp.async pipeline.
// mode 0: C fp32 (Wo projection)
// mode 4: fused QKV. blockIdx.x<16 -> Q (RoPE*QSCALE -> g_q),
//         16..19 -> K (RoPE -> g_k), 20..23 -> V (-> g_v)
// ---------------------------------------------------------------------------
#define A_ST 40
#define B_ST 136
#define A_SZ (128 * A_ST)
#define B_SZ (32 * B_ST)
#define GSMEM (4 * (A_SZ + B_SZ) * 2)

__global__ __launch_bounds__(256, 2) void gemm_f16(
    const __half* __restrict__ A, const __half* __restrict__ B0,
    const __half* __restrict__ B1, const __half* __restrict__ B2,
    float* __restrict__ C, int K, int mode)
{
    extern __shared__ __half smem[];
    __half* As = smem;
    __half* Bs = smem + 4 * A_SZ;

    const int tid = threadIdx.x, lane = tid & 31, wid = tid >> 5;
    const int wm = wid & 3, wn = wid >> 2;
    const int g = lane >> 2, t = lane & 3;
    const int m0 = blockIdx.y * 128;
    int n0 = blockIdx.x * 128;
    const __half* Bm = B0;
    int Nb = DM;
    int vmode = mode;
    if (mode == 4) {
        if (blockIdx.x < 16) {
            vmode = 1;                                    // Q
        } else if (blockIdx.x < 20) {
            Bm = B1; Nb = 512; n0 = (blockIdx.x - 16) * 128; vmode = 2;  // K
        } else {
            Bm = B2; Nb = 512; n0 = (blockIdx.x - 20) * 128; vmode = 3;  // V
        }
    }

    const uint32_t sA = smem_u32(As), sB = smem_u32(Bs);

    float acc[2][8][4];
#pragma unroll
    for (int mf = 0; mf < 2; mf++)
#pragma unroll
        for (int nt = 0; nt < 8; nt++)
#pragma unroll
            for (int r = 0; r < 4; r++) acc[mf][nt][r] = 0.f;

    auto issue = [&](int it) {
        int kt = it * 32, st = it & 3;
#pragma unroll
        for (int u = 0; u < 2; u++) {
            int c = tid + 256 * u;
            int r = c >> 2, q = c & 3;
            cp16(sA + (st * A_SZ + r * A_ST + q * 8) * 2,
                 &A[(size_t)(m0 + r) * K + kt + q * 8]);
        }
#pragma unroll
        for (int u = 0; u < 2; u++) {
            int c = tid + 256 * u;
            int r = c >> 4, q = c & 15;
            cp16(sB + (st * B_SZ + r * B_ST + q * 8) * 2,
                 &Bm[(size_t)(kt + r) * Nb + n0 + q * 8]);
        }
    };

    const int niter = K >> 5;
    issue(0); CP_COMMIT();
    issue(1); CP_COMMIT();
    issue(2); CP_COMMIT();

    for (int i = 0; i < niter; i++) {
        CP_WAIT(2);
        __syncthreads();
        const int st = i & 3;
        const uint32_t ab = sA + st * A_SZ * 2;
        const uint32_t bb = sB + st * B_SZ * 2;
#pragma unroll
        for (int ks = 0; ks < 2; ks++) {
            const int kb = ks * 16;
            uint32_t af[2][4], bf[8][2];
#pragma unroll
            for (int mf = 0; mf < 2; mf++)
                ldmx4(af[mf], ab + ((wm * 32 + mf * 16 + (lane & 15)) * A_ST +
                                    kb + (lane >> 4) * 8) * 2);
#pragma unroll
            for (int p = 0; p < 4; p++) {
                uint32_t r[4];
                ldmx4t(r, bb + ((kb + (lane & 15)) * B_ST +
                                wn * 64 + p * 16 + (lane >> 4) * 8) * 2);
                bf[2 * p][0] = r[0]; bf[2 * p][1] = r[1];
                bf[2 * p + 1][0] = r[2]; bf[2 * p + 1][1] = r[3];
            }
#pragma unroll
            for (int mf = 0; mf < 2; mf++)
#pragma unroll
                for (int nt = 0; nt < 8; nt++)
                    mma_f16(acc[mf][nt], af[mf], bf[nt]);
        }
        if (i + 3 < niter) issue(i + 3);
        CP_COMMIT();
    }

    // ---------------- epilogue ----------------
    if (mode == 0) {
#pragma unroll
        for (int mf = 0; mf < 2; mf++) {
            int r = m0 + wm * 32 + mf * 16 + g;
#pragma unroll
            for (int nt = 0; nt < 8; nt++) {
                int col = n0 + wn * 64 + nt * 8 + t * 2;
                *(float2*)&C[(size_t)r * DM + col] =
                    make_float2(acc[mf][nt][0], acc[mf][nt][1]);
                *(float2*)&C[(size_t)(r + 8) * DM + col] =
                    make_float2(acc[mf][nt][2], acc[mf][nt][3]);
            }
        }
        return;
    }

#pragma unroll
    for (int mf = 0; mf < 2; mf++) {
#pragma unroll
        for (int hh = 0; hh < 2; hh++) {
            int row = m0 + wm * 32 + mf * 16 + g + hh * 8;
            int b = row >> 11;
            int s = row & (SEQ - 1);
#pragma unroll
            for (int nt = 0; nt < 8; nt++) {
                int col = n0 + wn * 64 + nt * 8 + t * 2;   // even
                float v0 = acc[mf][nt][hh * 2 + 0];
                float v1 = acc[mf][nt][hh * 2 + 1];
                int d0 = col & 63;
                if (vmode != 3) {
                    int j0 = d0 & 31, j1 = (d0 + 1) & 31;
                    float2 cs0 = *(const float2*)&g_rope[((size_t)s * 32 + j0) * 2];
                    float2 cs1 = *(const float2*)&g_rope[((size_t)s * 32 + j1) * 2];
                    float o0 = v0 * cs0.x - v1 * cs0.y;
                    float o1 = v1 * cs1.x + v0 * cs1.y;
                    if (vmode == 1) { o0 *= QSCALE; o1 *= QSCALE; }
                    v0 = o0; v1 = o1;
                }
                int h = col >> 6;
                __half2 hv = __floats2half2_rn(v0, v1);
                if (vmode == 1)
                    *(__half2*)&g_q[(((size_t)b * NUM_HEADS + h) * SEQ + s) * HD + d0] = hv;
                else if (vmode == 2)
                    *(__half2*)&g_k[(((size_t)b * NUM_KV + h) * SEQ + s) * HD + d0] = hv;
                else
                    *(__half2*)&g_v[(((size_t)b * NUM_KV + h) * SEQ + s) * HD + d0] = hv;
            }
        }
    }
}

// ---------------------------------------------------------------------------
// fp16 mma flash attention. Q tile 128 (8 warps x 16 rows), KV tile 64,
// double-buffered cp.async K/V. Softmax scale pre-folded into Q.
// Heavy-first scheduling: blockIdx.x reversed.
// ---------------------------------------------------------------------------
#define FSTR 72

__global__ __launch_bounds__(256) void fa_f16()
{
    extern __shared__ __half sm[];
    __half* q_s = sm;                        // [128][72]
    __half* k_s = sm + 128 * FSTR;           // [2][64][72]
    __half* v_s = sm + 128 * FSTR + 2 * 64 * FSTR;

    const int tid = threadIdx.x, lane = tid & 31, w = tid >> 5;
    const int g = lane >> 2, t = lane & 3;
    const int qs = ((int)gridDim.x - 1 - (int)blockIdx.x) * 128;  // heavy first
    const int h = blockIdx.y, b = blockIdx.z;
    const int kvh = h >> 2;

    const __half* qg = &g_q[(((size_t)b * NUM_HEADS + h) * SEQ + qs) * HD];
    const __half* kg = &g_k[(((size_t)b * NUM_KV + kvh) * SEQ) * HD];
    const __half* vg = &g_v[(((size_t)b * NUM_KV + kvh) * SEQ) * HD];

    const uint32_t sq = smem_u32(q_s), sk = smem_u32(k_s), sv = smem_u32(v_s);

#pragma unroll
    for (int u = 0; u < 4; u++) {
        int c = tid + 256 * u;
        int r = c >> 3, q = c & 7;
        cp16(sq + (r * FSTR + q * 8) * 2, qg + (size_t)r * 64 + q * 8);
    }
    auto issue_kv = [&](int it) {
        int st = it & 1, koff = it * 64;
#pragma unroll
        for (int u = 0; u < 2; u++) {
            int c = tid + 256 * u;
            int r = c >> 3, q = c & 7;
            cp16(sk + (st * 64 * FSTR + r * FSTR + q * 8) * 2,
                 kg + (size_t)(koff + r) * 64 + q * 8);
            cp16(sv + (st * 64 * FSTR + r * FSTR + q * 8) * 2,
                 vg + (size_t)(koff + r) * 64 + q * 8);
        }
    };
    const int ntiles = qs / 64 + 2;
    issue_kv(0); CP_COMMIT();
    if (ntiles > 1) issue_kv(1);
    CP_COMMIT();

    float o[8][4];
#pragma unroll
    for (int p = 0; p < 8; p++)
#pragma unroll
        for (int r = 0; r < 4; r++) o[p][r] = 0.f;
    float m0r = -1e30f, m1r = -1e30f, l0 = 0.f, l1 = 0.f;
    uint32_t qf[4][4];

    for (int it = 0; it < ntiles; it++) {
        CP_WAIT(1);
        __syncthreads();
        if (it == 0) {
#pragma unroll
            for (int kc = 0; kc < 4; kc++)
                ldmx4(qf[kc], sq + ((w * 16 + (lane & 15)) * FSTR +
                                    kc * 16 + (lane >> 4) * 8) * 2);
        }
        const uint32_t kb = sk + ((it & 1) * 64 * FSTR) * 2;
        const uint32_t vb = sv + ((it & 1) * 64 * FSTR) * 2;

        // S = Q @ K^T (scale pre-folded into Q)
        float s[8][4];
#pragma unroll
        for (int p = 0; p < 8; p++)
#pragma unroll
            for (int r = 0; r < 4; r++) s[p][r] = 0.f;
#pragma unroll
        for (int kc = 0; kc < 4; kc++) {
#pragma unroll
            for (int p = 0; p < 4; p++) {
                uint32_t r[4];
                ldmx4(r, kb + ((p * 16 + (lane & 7) + ((lane >> 4) & 1) * 8) * FSTR +
                               kc * 16 + ((lane >> 3) & 1) * 8) * 2);
                mma_f16(s[2 * p], qf[kc], r);
                mma_f16(s[2 * p + 1], qf[kc], r + 2);
            }
        }

        // causal mask on boundary tiles
        const int kt = it * 64;
        const int rowg = qs + w * 16 + g;
        if (kt + 63 > qs + w * 16) {
#pragma unroll
            for (int p = 0; p < 8; p++) {
                int col = kt + p * 8 + 2 * t;
                if (col > rowg)     s[p][0] = -1e30f;
                if (col + 1 > rowg) s[p][1] = -1e30f;
                if (col > rowg + 8)     s[p][2] = -1e30f;
                if (col + 1 > rowg + 8) s[p][3] = -1e30f;
            }
        }

        // online softmax (rows g and g+8), quad reductions
        float mx0 = -1e30f, mx1 = -1e30f;
#pragma unroll
        for (int p = 0; p < 8; p++) {
            mx0 = fmaxf(mx0, fmaxf(s[p][0], s[p][1]));
            mx1 = fmaxf(mx1, fmaxf(s[p][2], s[p][3]));
        }
        mx0 = fmaxf(mx0, __shfl_xor_sync(0xffffffffu, mx0, 1));
        mx0 = fmaxf(mx0, __shfl_xor_sync(0xffffffffu, mx0, 2));
        mx1 = fmaxf(mx1, __shfl_xor_sync(0xffffffffu, mx1, 1));
        mx1 = fmaxf(mx1, __shfl_xor_sync(0xffffffffu, mx1, 2));
        float mn0 = fmaxf(m0r, mx0), mn1 = fmaxf(m1r, mx1);
        float a0 = ex2(m0r - mn0), a1 = ex2(m1r - mn1);
        m0r = mn0; m1r = mn1;

        float ps0 = 0.f, ps1 = 0.f;
        uint32_t pf[4][4];
#pragma unroll
        for (int p = 0; p < 8; p++) {
            float p0 = ex2(s[p][0] - mn0);
            float p1 = ex2(s[p][1] - mn0);
            float p2 = ex2(s[p][2] - mn1);
            float p3 = ex2(s[p][3] - mn1);
            ps0 += p0 + p1;
            ps1 += p2 + p3;
            int kc = p >> 1;
            if ((p & 1) == 0) {
                pf[kc][0] = packh2(p0, p1);
                pf[kc][1] = packh2(p2, p3);
            } else {
                pf[kc][2] = packh2(p0, p1);
                pf[kc][3] = packh2(p2, p3);
            }
        }
        ps0 += __shfl_xor_sync(0xffffffffu, ps0, 1);
        ps0 += __shfl_xor_sync(0xffffffffu, ps0, 2);
        ps1 += __shfl_xor_sync(0xffffffffu, ps1, 1);
        ps1 += __shfl_xor_sync(0xffffffffu, ps1, 2);
        l0 = l0 * a0 + ps0;
        l1 = l1 * a1 + ps1;
#pragma unroll
        for (int p = 0; p < 8; p++) {
            o[p][0] *= a0; o[p][1] *= a0;
            o[p][2] *= a1; o[p][3] *= a1;
        }

        // O += P @ V
#pragma unroll
        for (int kc = 0; kc < 4; kc++) {
#pragma unroll
            for (int p = 0; p < 4; p++) {
                uint32_t r[4];
                ldmx4t(r, vb + ((kc * 16 + (lane & 15)) * FSTR +
                                p * 16 + ((lane >> 4) & 1) * 8) * 2);
                mma_f16(o[2 * p], pf[kc], r);
                mma_f16(o[2 * p + 1], pf[kc], r + 2);
            }
        }

        __syncthreads();
        if (it + 2 < ntiles) issue_kv(it + 2);
        CP_COMMIT();
    }

    // epilogue
    float inv0 = 1.f / l0, inv1 = 1.f / l1;
    __half* og = &g_ao[((size_t)(b * SEQ + qs + w * 16)) * DM + h * HD];
#pragma unroll
    for (int p = 0; p < 8; p++) {
        int col = p * 8 + 2 * t;
        *(__half2*)&og[(size_t)g * DM + col] =
            __floats2half2_rn(o[p][0] * inv0, o[p][1] * inv0);
        *(__half2*)&og[(size_t)(g + 8) * DM + col] =
            __floats2half2_rn(o[p][2] * inv1, o[p][3] * inv1);
    }
}

// ---------------------------------------------------------------------------

extern "C" void kernel_launch(void* const* d_in, const int* in_sizes, int n_in,
                              void* d_out, int out_size)
{
    const float* x  = (const float*)d_in[0];
    const float* Wq = (const float*)d_in[2];
    const float* Wk = (const float*)d_in[3];
    const float* Wv = (const float*)d_in[4];
    const float* Wo = (const float*)d_in[5];
    float* out = (float*)d_out;

    void *xh, *wq, *wk, *wv, *wo, *ao;
    cudaGetSymbolAddress(&xh, g_xh);
    cudaGetSymbolAddress(&wq, g_wq);
    cudaGetSymbolAddress(&wk, g_wk);
    cudaGetSymbolAddress(&wv, g_wv);
    cudaGetSymbolAddress(&wo, g_wo);
    cudaGetSymbolAddress(&ao, g_ao);

    cudaFuncSetAttribute(gemm_f16, cudaFuncAttributeMaxDynamicSharedMemorySize, GSMEM);
    cudaFuncSetAttribute(fa_f16, cudaFuncAttributeMaxDynamicSharedMemorySize,
                         (128 + 4 * 64) * FSTR * 2);

    // fp32 -> fp16 conversions
    f2h<<<(MTOT * DM / 4 + 255) / 256, 256>>>((const float4*)x, (__half*)xh, MTOT * DM / 4);
    f2h<<<(DM * DM / 4 + 255) / 256, 256>>>((const float4*)Wq, (__half*)wq, DM * DM / 4);
    f2h<<<(DM * 512 / 4 + 255) / 256, 256>>>((const float4*)Wk, (__half*)wk, DM * 512 / 4);
    f2h<<<(DM * 512 / 4 + 255) / 256, 256>>>((const float4*)Wv, (__half*)wv, DM * 512 / 4);
    f2h<<<(DM * DM / 4 + 255) / 256, 256>>>((const float4*)Wo, (__half*)wo, DM * DM / 4);

    rope_init<<<(SEQ * 32) / 256, 256>>>();

    // fused Q+K+V projections (RoPE on Q/K, scale folded into Q)
    gemm_f16<<<dim3(24, MTOT / 128), 256, GSMEM>>>(
        (const __half*)xh, (const __half*)wq, (const __half*)wk,
        (const __half*)wv, nullptr, DM, 4);

    // flash attention (heavy-first)
    fa_f16<<<dim3(SEQ / 128, NUM_HEADS, B_DIM), 256, (128 + 4 * 64) * FSTR * 2>>>();

    // output projection
    gemm_f16<<<dim3(DM / 128, MTOT / 128), 256, GSMEM>>>(
        (const __half*)ao, (const __half*)wo, nullptr, nullptr, out, DM, 0);
}

// round 7
// speedup vs baseline: 4.6635x; 1.0192x over previous
#include <cuda_runtime.h>
#include <cuda_fp16.h>
#include <math.h>
#include <stdint.h>

#define B_DIM 2
#define NUM_HEADS 32
#define NUM_KV 8
#define SEQ 2048
#define DM 2048
#define HD 64
#define MTOT (B_DIM * SEQ)

// fp16 scratch (allocation-free device globals)
__device__ __half g_xh[(size_t)MTOT * DM];
__device__ __half g_wq[(size_t)DM * DM];
__device__ __half g_wk[(size_t)DM * 512];
__device__ __half g_wv[(size_t)DM * 512];
__device__ __half g_wo[(size_t)DM * DM];
__device__ __half g_q[(size_t)B_DIM * NUM_HEADS * SEQ * HD];
__device__ __half g_k[(size_t)B_DIM * NUM_KV * SEQ * HD];
__device__ __half g_v[(size_t)B_DIM * NUM_KV * SEQ * HD];
__device__ __half g_ao[(size_t)MTOT * DM];
__device__ float  g_rope[SEQ * 32 * 2];

// softmax scale folded into Q at projection time: 1/sqrt(64) * log2(e)
#define QSCALE 0.1803368801111204f

// ---------------------------------------------------------------------------
// Fused prologue: all fp32->fp16 conversions + RoPE table in ONE launch.
// Block ranges (each segment size divisible by 256 blocks):
//   [0,8192)      x  -> g_xh   (2,097,152 float4)
//   [8192,12288)  Wq -> g_wq   (1,048,576)
//   [12288,13312) Wk -> g_wk   (262,144)
//   [13312,14336) Wv -> g_wv   (262,144)
//   [14336,18432) Wo -> g_wo   (1,048,576)
//   [18432,18688) rope table   (65,536 entries)
// ---------------------------------------------------------------------------
__global__ void prep(const float4* __restrict__ x, const float4* __restrict__ wq,
                     const float4* __restrict__ wk, const float4* __restrict__ wv,
                     const float4* __restrict__ wo)
{
    const int b = blockIdx.x, tid = threadIdx.x;
    const float4* src;
    __half* dst;
    int base;
    if (b < 8192)       { src = x;  dst = g_xh; base = 0; }
    else if (b < 12288) { src = wq; dst = g_wq; base = 8192; }
    else if (b < 13312) { src = wk; dst = g_wk; base = 12288; }
    else if (b < 14336) { src = wv; dst = g_wv; base = 13312; }
    else if (b < 18432) { src = wo; dst = g_wo; base = 14336; }
    else {
        int i = (b - 18432) * 256 + tid;
        int s = i >> 5, j = i & 31;
        float inv = expf(-(float)j * 0.28782313662425572f);
        float sv, cv;
        sincosf((float)s * inv, &sv, &cv);
        g_rope[(size_t)i * 2 + 0] = cv;
        g_rope[(size_t)i * 2 + 1] = sv;
        return;
    }
    size_t i = (size_t)(b - base) * 256 + tid;
    float4 v = src[i];
    __half2* d = (__half2*)(dst + i * 4);
    d[0] = __floats2half2_rn(v.x, v.y);
    d[1] = __floats2half2_rn(v.z, v.w);
}

// ---------------------------------------------------------------------------
// Helpers
// ---------------------------------------------------------------------------
__device__ __forceinline__ uint32_t smem_u32(const void* p)
{
    return (uint32_t)__cvta_generic_to_shared(p);
}
__device__ __forceinline__ void ldmx4(uint32_t* r, uint32_t a)
{
    asm volatile("ldmatrix.sync.aligned.m8n8.x4.shared.b16 {%0,%1,%2,%3}, [%4];"
                 : "=r"(r[0]), "=r"(r[1]), "=r"(r[2]), "=r"(r[3]) : "r"(a));
}
__device__ __forceinline__ void ldmx4t(uint32_t* r, uint32_t a)
{
    asm volatile("ldmatrix.sync.aligned.m8n8.x4.trans.shared.b16 {%0,%1,%2,%3}, [%4];"
                 : "=r"(r[0]), "=r"(r[1]), "=r"(r[2]), "=r"(r[3]) : "r"(a));
}
__device__ __forceinline__ void mma_f16(float* c, const uint32_t* a, const uint32_t* b)
{
    asm volatile(
        "mma.sync.aligned.m16n8k16.row.col.f32.f16.f16.f32 "
        "{%0,%1,%2,%3}, {%4,%5,%6,%7}, {%8,%9}, {%0,%1,%2,%3};"
        : "+f"(c[0]), "+f"(c[1]), "+f"(c[2]), "+f"(c[3])
        : "r"(a[0]), "r"(a[1]), "r"(a[2]), "r"(a[3]), "r"(b[0]), "r"(b[1]));
}
__device__ __forceinline__ void cp16(uint32_t saddr, const void* g)
{
    asm volatile("cp.async.cg.shared.global [%0], [%1], 16;" :: "r"(saddr), "l"(g));
}
#define CP_COMMIT() asm volatile("cp.async.commit_group;")
#define CP_WAIT(n)  asm volatile("cp.async.wait_group %0;" :: "n"(n))

__device__ __forceinline__ float ex2(float x)
{
    float r;
    asm("ex2.approx.ftz.f32 %0, %1;" : "=f"(r) : "f"(x));
    return r;
}
// packed fp16x2 exp2 — halves MUFU traffic in the softmax
__device__ __forceinline__ uint32_t ex2h2(uint32_t x)
{
    uint32_t r;
    asm("ex2.approx.f16x2 %0, %1;" : "=r"(r) : "r"(x));
    return r;
}
__device__ __forceinline__ uint32_t packh2(float lo, float hi)
{
    __half2 h = __floats2half2_rn(lo, hi);
    return *reinterpret_cast<uint32_t*>(&h);
}

// ---------------------------------------------------------------------------
// fp16 GEMM, CTA 128x128, BK=32, 8 warps (4m x 2n, warp tile 32x64),
// 4-stage cp.async pipeline.
// mode 0: C fp32 (Wo projection)
// mode 4: fused QKV. blockIdx.x<16 -> Q (RoPE*QSCALE -> g_q),
//         16..19 -> K (RoPE -> g_k), 20..23 -> V (-> g_v)
// ---------------------------------------------------------------------------
#define A_ST 40
#define B_ST 136
#define A_SZ (128 * A_ST)
#define B_SZ (32 * B_ST)
#define GSMEM (4 * (A_SZ + B_SZ) * 2)

__global__ __launch_bounds__(256, 2) void gemm_f16(
    const __half* __restrict__ A, const __half* __restrict__ B0,
    const __half* __restrict__ B1, const __half* __restrict__ B2,
    float* __restrict__ C, int K, int mode)
{
    extern __shared__ __half smem[];
    __half* As = smem;
    __half* Bs = smem + 4 * A_SZ;

    const int tid = threadIdx.x, lane = tid & 31, wid = tid >> 5;
    const int wm = wid & 3, wn = wid >> 2;
    const int g = lane >> 2, t = lane & 3;
    const int m0 = blockIdx.y * 128;
    int n0 = blockIdx.x * 128;
    const __half* Bm = B0;
    int Nb = DM;
    int vmode = mode;
    if (mode == 4) {
        if (blockIdx.x < 16) {
            vmode = 1;                                    // Q
        } else if (blockIdx.x < 20) {
            Bm = B1; Nb = 512; n0 = (blockIdx.x - 16) * 128; vmode = 2;  // K
        } else {
            Bm = B2; Nb = 512; n0 = (blockIdx.x - 20) * 128; vmode = 3;  // V
        }
    }

    const uint32_t sA = smem_u32(As), sB = smem_u32(Bs);

    float acc[2][8][4];
#pragma unroll
    for (int mf = 0; mf < 2; mf++)
#pragma unroll
        for (int nt = 0; nt < 8; nt++)
#pragma unroll
            for (int r = 0; r < 4; r++) acc[mf][nt][r] = 0.f;

    auto issue = [&](int it) {
        int kt = it * 32, st = it & 3;
#pragma unroll
        for (int u = 0; u < 2; u++) {
            int c = tid + 256 * u;
            int r = c >> 2, q = c & 3;
            cp16(sA + (st * A_SZ + r * A_ST + q * 8) * 2,
                 &A[(size_t)(m0 + r) * K + kt + q * 8]);
        }
#pragma unroll
        for (int u = 0; u < 2; u++) {
            int c = tid + 256 * u;
            int r = c >> 4, q = c & 15;
            cp16(sB + (st * B_SZ + r * B_ST + q * 8) * 2,
                 &Bm[(size_t)(kt + r) * Nb + n0 + q * 8]);
        }
    };

    const int niter = K >> 5;
    issue(0); CP_COMMIT();
    issue(1); CP_COMMIT();
    issue(2); CP_COMMIT();

    for (int i = 0; i < niter; i++) {
        CP_WAIT(2);
        __syncthreads();
        const int st = i & 3;
        const uint32_t ab = sA + st * A_SZ * 2;
        const uint32_t bb = sB + st * B_SZ * 2;
#pragma unroll
        for (int ks = 0; ks < 2; ks++) {
            const int kb = ks * 16;
            uint32_t af[2][4], bf[8][2];
#pragma unroll
            for (int mf = 0; mf < 2; mf++)
                ldmx4(af[mf], ab + ((wm * 32 + mf * 16 + (lane & 15)) * A_ST +
                                    kb + (lane >> 4) * 8) * 2);
#pragma unroll
            for (int p = 0; p < 4; p++) {
                uint32_t r[4];
                ldmx4t(r, bb + ((kb + (lane & 15)) * B_ST +
                                wn * 64 + p * 16 + (lane >> 4) * 8) * 2);
                bf[2 * p][0] = r[0]; bf[2 * p][1] = r[1];
                bf[2 * p + 1][0] = r[2]; bf[2 * p + 1][1] = r[3];
            }
#pragma unroll
            for (int mf = 0; mf < 2; mf++)
#pragma unroll
                for (int nt = 0; nt < 8; nt++)
                    mma_f16(acc[mf][nt], af[mf], bf[nt]);
        }
        if (i + 3 < niter) issue(i + 3);
        CP_COMMIT();
    }

    // ---------------- epilogue ----------------
    if (mode == 0) {
#pragma unroll
        for (int mf = 0; mf < 2; mf++) {
            int r = m0 + wm * 32 + mf * 16 + g;
#pragma unroll
            for (int nt = 0; nt < 8; nt++) {
                int col = n0 + wn * 64 + nt * 8 + t * 2;
                *(float2*)&C[(size_t)r * DM + col] =
                    make_float2(acc[mf][nt][0], acc[mf][nt][1]);
                *(float2*)&C[(size_t)(r + 8) * DM + col] =
                    make_float2(acc[mf][nt][2], acc[mf][nt][3]);
            }
        }
        return;
    }

#pragma unroll
    for (int mf = 0; mf < 2; mf++) {
#pragma unroll
        for (int hh = 0; hh < 2; hh++) {
            int row = m0 + wm * 32 + mf * 16 + g + hh * 8;
            int b = row >> 11;
            int s = row & (SEQ - 1);
#pragma unroll
            for (int nt = 0; nt < 8; nt++) {
                int col = n0 + wn * 64 + nt * 8 + t * 2;   // even
                float v0 = acc[mf][nt][hh * 2 + 0];
                float v1 = acc[mf][nt][hh * 2 + 1];
                int d0 = col & 63;
                if (vmode != 3) {
                    int j0 = d0 & 31, j1 = (d0 + 1) & 31;
                    float2 cs0 = *(const float2*)&g_rope[((size_t)s * 32 + j0) * 2];
                    float2 cs1 = *(const float2*)&g_rope[((size_t)s * 32 + j1) * 2];
                    float o0 = v0 * cs0.x - v1 * cs0.y;
                    float o1 = v1 * cs1.x + v0 * cs1.y;
                    if (vmode == 1) { o0 *= QSCALE; o1 *= QSCALE; }
                    v0 = o0; v1 = o1;
                }
                int h = col >> 6;
                __half2 hv = __floats2half2_rn(v0, v1);
                if (vmode == 1)
                    *(__half2*)&g_q[(((size_t)b * NUM_HEADS + h) * SEQ + s) * HD + d0] = hv;
                else if (vmode == 2)
                    *(__half2*)&g_k[(((size_t)b * NUM_KV + h) * SEQ + s) * HD + d0] = hv;
                else
                    *(__half2*)&g_v[(((size_t)b * NUM_KV + h) * SEQ + s) * HD + d0] = hv;
            }
        }
    }
}

// ---------------------------------------------------------------------------
// fp16 mma flash attention. Q tile 128 (8 warps x 16 rows), KV tile 64,
// double-buffered cp.async K/V. Softmax scale pre-folded into Q.
// exp in packed fp16x2 (MUFU traffic halved); row sums via HADD2 chain.
// Heavy-first scheduling: blockIdx.x reversed.
// ---------------------------------------------------------------------------
#define FSTR 72

__global__ __launch_bounds__(256) void fa_f16()
{
    extern __shared__ __half sm[];
    __half* q_s = sm;                        // [128][72]
    __half* k_s = sm + 128 * FSTR;           // [2][64][72]
    __half* v_s = sm + 128 * FSTR + 2 * 64 * FSTR;

    const int tid = threadIdx.x, lane = tid & 31, w = tid >> 5;
    const int g = lane >> 2, t = lane & 3;
    const int qs = ((int)gridDim.x - 1 - (int)blockIdx.x) * 128;  // heavy first
    const int h = blockIdx.y, b = blockIdx.z;
    const int kvh = h >> 2;

    const __half* qg = &g_q[(((size_t)b * NUM_HEADS + h) * SEQ + qs) * HD];
    const __half* kg = &g_k[(((size_t)b * NUM_KV + kvh) * SEQ) * HD];
    const __half* vg = &g_v[(((size_t)b * NUM_KV + kvh) * SEQ) * HD];

    const uint32_t sq = smem_u32(q_s), sk = smem_u32(k_s), sv = smem_u32(v_s);

#pragma unroll
    for (int u = 0; u < 4; u++) {
        int c = tid + 256 * u;
        int r = c >> 3, q = c & 7;
        cp16(sq + (r * FSTR + q * 8) * 2, qg + (size_t)r * 64 + q * 8);
    }
    auto issue_kv = [&](int it) {
        int st = it & 1, koff = it * 64;
#pragma unroll
        for (int u = 0; u < 2; u++) {
            int c = tid + 256 * u;
            int r = c >> 3, q = c & 7;
            cp16(sk + (st * 64 * FSTR + r * FSTR + q * 8) * 2,
                 kg + (size_t)(koff + r) * 64 + q * 8);
            cp16(sv + (st * 64 * FSTR + r * FSTR + q * 8) * 2,
                 vg + (size_t)(koff + r) * 64 + q * 8);
        }
    };
    const int ntiles = qs / 64 + 2;
    issue_kv(0); CP_COMMIT();
    if (ntiles > 1) issue_kv(1);
    CP_COMMIT();

    float o[8][4];
#pragma unroll
    for (int p = 0; p < 8; p++)
#pragma unroll
        for (int r = 0; r < 4; r++) o[p][r] = 0.f;
    float m0r = -1e30f, m1r = -1e30f, l0 = 0.f, l1 = 0.f;
    uint32_t qf[4][4];

    for (int it = 0; it < ntiles; it++) {
        CP_WAIT(1);
        __syncthreads();
        if (it == 0) {
#pragma unroll
            for (int kc = 0; kc < 4; kc++)
                ldmx4(qf[kc], sq + ((w * 16 + (lane & 15)) * FSTR +
                                    kc * 16 + (lane >> 4) * 8) * 2);
        }
        const uint32_t kb = sk + ((it & 1) * 64 * FSTR) * 2;
        const uint32_t vb = sv + ((it & 1) * 64 * FSTR) * 2;

        // S = Q @ K^T (scale pre-folded into Q)
        float s[8][4];
#pragma unroll
        for (int p = 0; p < 8; p++)
#pragma unroll
            for (int r = 0; r < 4; r++) s[p][r] = 0.f;
#pragma unroll
        for (int kc = 0; kc < 4; kc++) {
#pragma unroll
            for (int p = 0; p < 4; p++) {
                uint32_t r[4];
                ldmx4(r, kb + ((p * 16 + (lane & 7) + ((lane >> 4) & 1) * 8) * FSTR +
                               kc * 16 + ((lane >> 3) & 1) * 8) * 2);
                mma_f16(s[2 * p], qf[kc], r);
                mma_f16(s[2 * p + 1], qf[kc], r + 2);
            }
        }

        // causal mask on boundary tiles
        const int kt = it * 64;
        const int rowg = qs + w * 16 + g;
        if (kt + 63 > qs + w * 16) {
#pragma unroll
            for (int p = 0; p < 8; p++) {
                int col = kt + p * 8 + 2 * t;
                if (col > rowg)     s[p][0] = -1e30f;
                if (col + 1 > rowg) s[p][1] = -1e30f;
                if (col > rowg + 8)     s[p][2] = -1e30f;
                if (col + 1 > rowg + 8) s[p][3] = -1e30f;
            }
        }

        // online softmax (rows g and g+8)
        float mx0 = -1e30f, mx1 = -1e30f;
#pragma unroll
        for (int p = 0; p < 8; p++) {
            mx0 = fmaxf(mx0, fmaxf(s[p][0], s[p][1]));
            mx1 = fmaxf(mx1, fmaxf(s[p][2], s[p][3]));
        }
        mx0 = fmaxf(mx0, __shfl_xor_sync(0xffffffffu, mx0, 1));
        mx0 = fmaxf(mx0, __shfl_xor_sync(0xffffffffu, mx0, 2));
        mx1 = fmaxf(mx1, __shfl_xor_sync(0xffffffffu, mx1, 1));
        mx1 = fmaxf(mx1, __shfl_xor_sync(0xffffffffu, mx1, 2));
        float mn0 = fmaxf(m0r, mx0), mn1 = fmaxf(m1r, mx1);
        float a0 = ex2(m0r - mn0), a1 = ex2(m1r - mn1);
        m0r = mn0; m1r = mn1;

        // exp in packed fp16 (same values feed the mma AND the row sum)
        __half2 acc0 = __floats2half2_rn(0.f, 0.f);
        __half2 acc1 = acc0;
        uint32_t pf[4][4];
#pragma unroll
        for (int p = 0; p < 8; p++) {
            uint32_t e0 = ex2h2(packh2(s[p][0] - mn0, s[p][1] - mn0));
            uint32_t e1 = ex2h2(packh2(s[p][2] - mn1, s[p][3] - mn1));
            acc0 = __hadd2(acc0, *reinterpret_cast<__half2*>(&e0));
            acc1 = __hadd2(acc1, *reinterpret_cast<__half2*>(&e1));
            int kc = p >> 1;
            if ((p & 1) == 0) { pf[kc][0] = e0; pf[kc][1] = e1; }
            else              { pf[kc][2] = e0; pf[kc][3] = e1; }
        }
        float ps0 = __low2float(acc0) + __high2float(acc0);
        float ps1 = __low2float(acc1) + __high2float(acc1);
        ps0 += __shfl_xor_sync(0xffffffffu, ps0, 1);
        ps0 += __shfl_xor_sync(0xffffffffu, ps0, 2);
        ps1 += __shfl_xor_sync(0xffffffffu, ps1, 1);
        ps1 += __shfl_xor_sync(0xffffffffu, ps1, 2);
        l0 = l0 * a0 + ps0;
        l1 = l1 * a1 + ps1;
#pragma unroll
        for (int p = 0; p < 8; p++) {
            o[p][0] *= a0; o[p][1] *= a0;
            o[p][2] *= a1; o[p][3] *= a1;
        }

        // O += P @ V
#pragma unroll
        for (int kc = 0; kc < 4; kc++) {
#pragma unroll
            for (int p = 0; p < 4; p++) {
                uint32_t r[4];
                ldmx4t(r, vb + ((kc * 16 + (lane & 15)) * FSTR +
                                p * 16 + ((lane >> 4) & 1) * 8) * 2);
                mma_f16(o[2 * p], pf[kc], r);
                mma_f16(o[2 * p + 1], pf[kc], r + 2);
            }
        }

        __syncthreads();
        if (it + 2 < ntiles) issue_kv(it + 2);
        CP_COMMIT();
    }

    // epilogue
    float inv0 = 1.f / l0, inv1 = 1.f / l1;
    __half* og = &g_ao[((size_t)(b * SEQ + qs + w * 16)) * DM + h * HD];
#pragma unroll
    for (int p = 0; p < 8; p++) {
        int col = p * 8 + 2 * t;
        *(__half2*)&og[(size_t)g * DM + col] =
            __floats2half2_rn(o[p][0] * inv0, o[p][1] * inv0);
        *(__half2*)&og[(size_t)(g + 8) * DM + col] =
            __floats2half2_rn(o[p][2] * inv1, o[p][3] * inv1);
    }
}

// ---------------------------------------------------------------------------

extern "C" void kernel_launch(void* const* d_in, const int* in_sizes, int n_in,
                              void* d_out, int out_size)
{
    const float* x  = (const float*)d_in[0];
    const float* Wq = (const float*)d_in[2];
    const float* Wk = (const float*)d_in[3];
    const float* Wv = (const float*)d_in[4];
    const float* Wo = (const float*)d_in[5];
    float* out = (float*)d_out;

    void *xh, *wq, *wk, *wv, *wo, *ao;
    cudaGetSymbolAddress(&xh, g_xh);
    cudaGetSymbolAddress(&wq, g_wq);
    cudaGetSymbolAddress(&wk, g_wk);
    cudaGetSymbolAddress(&wv, g_wv);
    cudaGetSymbolAddress(&wo, g_wo);
    cudaGetSymbolAddress(&ao, g_ao);

    cudaFuncSetAttribute(gemm_f16, cudaFuncAttributeMaxDynamicSharedMemorySize, GSMEM);
    cudaFuncSetAttribute(fa_f16, cudaFuncAttributeMaxDynamicSharedMemorySize,
                         (128 + 4 * 64) * FSTR * 2);

    // fused prologue: all conversions + rope table (one launch)
    prep<<<18688, 256>>>((const float4*)x, (const float4*)Wq, (const float4*)Wk,
                         (const float4*)Wv, (const float4*)Wo);

    // fused Q+K+V projections (RoPE on Q/K, scale folded into Q)
    gemm_f16<<<dim3(24, MTOT / 128), 256, GSMEM>>>(
        (const __half*)xh, (const __half*)wq, (const __half*)wk,
        (const __half*)wv, nullptr, DM, 4);

    // flash attention (heavy-first)
    fa_f16<<<dim3(SEQ / 128, NUM_HEADS, B_DIM), 256, (128 + 4 * 64) * FSTR * 2>>>();

    // output projection
    gemm_f16<<<dim3(DM / 128, MTOT / 128), 256, GSMEM>>>(
        (const __half*)ao, (const __half*)wo, nullptr, nullptr, out, DM, 0);
}

// round 8
// speedup vs baseline: 4.7124x; 1.0105x over previous
#include <cuda_runtime.h>
#include <cuda_fp16.h>
#include <math.h>
#include <stdint.h>

#define B_DIM 2
#define NUM_HEADS 32
#define NUM_KV 8
#define SEQ 2048
#define DM 2048
#define HD 64
#define MTOT (B_DIM * SEQ)

// fp16 scratch (allocation-free device globals)
__device__ __half g_xh[(size_t)MTOT * DM];
__device__ __half g_wq[(size_t)DM * DM];
__device__ __half g_wk[(size_t)DM * 512];
__device__ __half g_wv[(size_t)DM * 512];
__device__ __half g_wo[(size_t)DM * DM];
__device__ __half g_q[(size_t)B_DIM * NUM_HEADS * SEQ * HD];
__device__ __half g_k[(size_t)B_DIM * NUM_KV * SEQ * HD];
__device__ __half g_v[(size_t)B_DIM * NUM_KV * SEQ * HD];
__device__ __half g_ao[(size_t)MTOT * DM];
__device__ float  g_rope[SEQ * 32 * 2];

// softmax scale folded into Q at projection time: 1/sqrt(64) * log2(e)
#define QSCALE 0.1803368801111204f

// ---------------------------------------------------------------------------
// Fused prologue: all fp32->fp16 conversions + RoPE table in ONE launch.
// ---------------------------------------------------------------------------
__global__ void prep(const float4* __restrict__ x, const float4* __restrict__ wq,
                     const float4* __restrict__ wk, const float4* __restrict__ wv,
                     const float4* __restrict__ wo)
{
    const int b = blockIdx.x, tid = threadIdx.x;
    const float4* src;
    __half* dst;
    int base;
    if (b < 8192)       { src = x;  dst = g_xh; base = 0; }
    else if (b < 12288) { src = wq; dst = g_wq; base = 8192; }
    else if (b < 13312) { src = wk; dst = g_wk; base = 12288; }
    else if (b < 14336) { src = wv; dst = g_wv; base = 13312; }
    else if (b < 18432) { src = wo; dst = g_wo; base = 14336; }
    else {
        int i = (b - 18432) * 256 + tid;
        int s = i >> 5, j = i & 31;
        float inv = expf(-(float)j * 0.28782313662425572f);
        float sv, cv;
        sincosf((float)s * inv, &sv, &cv);
        g_rope[(size_t)i * 2 + 0] = cv;
        g_rope[(size_t)i * 2 + 1] = sv;
        return;
    }
    size_t i = (size_t)(b - base) * 256 + tid;
    float4 v = src[i];
    __half2* d = (__half2*)(dst + i * 4);
    d[0] = __floats2half2_rn(v.x, v.y);
    d[1] = __floats2half2_rn(v.z, v.w);
}

// ---------------------------------------------------------------------------
// Helpers
// ---------------------------------------------------------------------------
__device__ __forceinline__ uint32_t smem_u32(const void* p)
{
    return (uint32_t)__cvta_generic_to_shared(p);
}
__device__ __forceinline__ void ldmx4(uint32_t* r, uint32_t a)
{
    asm volatile("ldmatrix.sync.aligned.m8n8.x4.shared.b16 {%0,%1,%2,%3}, [%4];"
                 : "=r"(r[0]), "=r"(r[1]), "=r"(r[2]), "=r"(r[3]) : "r"(a));
}
__device__ __forceinline__ void ldmx4t(uint32_t* r, uint32_t a)
{
    asm volatile("ldmatrix.sync.aligned.m8n8.x4.trans.shared.b16 {%0,%1,%2,%3}, [%4];"
                 : "=r"(r[0]), "=r"(r[1]), "=r"(r[2]), "=r"(r[3]) : "r"(a));
}
__device__ __forceinline__ void mma_f16(float* c, const uint32_t* a, const uint32_t* b)
{
    asm volatile(
        "mma.sync.aligned.m16n8k16.row.col.f32.f16.f16.f32 "
        "{%0,%1,%2,%3}, {%4,%5,%6,%7}, {%8,%9}, {%0,%1,%2,%3};"
        : "+f"(c[0]), "+f"(c[1]), "+f"(c[2]), "+f"(c[3])
        : "r"(a[0]), "r"(a[1]), "r"(a[2]), "r"(a[3]), "r"(b[0]), "r"(b[1]));
}
__device__ __forceinline__ void cp16(uint32_t saddr, const void* g)
{
    asm volatile("cp.async.cg.shared.global [%0], [%1], 16;" :: "r"(saddr), "l"(g));
}
#define CP_COMMIT() asm volatile("cp.async.commit_group;")
#define CP_WAIT(n)  asm volatile("cp.async.wait_group %0;" :: "n"(n))

__device__ __forceinline__ float ex2(float x)
{
    float r;
    asm("ex2.approx.ftz.f32 %0, %1;" : "=f"(r) : "f"(x));
    return r;
}
__device__ __forceinline__ uint32_t ex2h2(uint32_t x)
{
    uint32_t r;
    asm("ex2.approx.f16x2 %0, %1;" : "=r"(r) : "r"(x));
    return r;
}
__device__ __forceinline__ uint32_t packh2(float lo, float hi)
{
    __half2 h = __floats2half2_rn(lo, hi);
    return *reinterpret_cast<uint32_t*>(&h);
}

// ---------------------------------------------------------------------------
// fp16 GEMM, CTA 128x128, BK=64 (128 HMMA between barriers), 8 warps
// (4m x 2n, warp tile 32x64), 3-stage cp.async pipeline, 2 CTAs/SM.
// mode 0: C fp32 (Wo projection)
// mode 4: fused QKV. blockIdx.x<16 -> Q (RoPE*QSCALE -> g_q),
//         16..19 -> K (RoPE -> g_k), 20..23 -> V (-> g_v)
// ---------------------------------------------------------------------------
#define A_ST 72
#define B_ST 136
#define A_SZ (128 * A_ST)
#define B_SZ (64 * B_ST)
#define GSMEM (3 * (A_SZ + B_SZ) * 2)

__global__ __launch_bounds__(256, 2) void gemm_f16(
    const __half* __restrict__ A, const __half* __restrict__ B0,
    const __half* __restrict__ B1, const __half* __restrict__ B2,
    float* __restrict__ C, int K, int mode)
{
    extern __shared__ __half smem[];
    __half* As = smem;
    __half* Bs = smem + 3 * A_SZ;

    const int tid = threadIdx.x, lane = tid & 31, wid = tid >> 5;
    const int wm = wid & 3, wn = wid >> 2;
    const int g = lane >> 2, t = lane & 3;
    const int m0 = blockIdx.y * 128;
    int n0 = blockIdx.x * 128;
    const __half* Bm = B0;
    int Nb = DM;
    int vmode = mode;
    if (mode == 4) {
        if (blockIdx.x < 16) {
            vmode = 1;                                    // Q
        } else if (blockIdx.x < 20) {
            Bm = B1; Nb = 512; n0 = (blockIdx.x - 16) * 128; vmode = 2;  // K
        } else {
            Bm = B2; Nb = 512; n0 = (blockIdx.x - 20) * 128; vmode = 3;  // V
        }
    }

    const uint32_t sA = smem_u32(As), sB = smem_u32(Bs);
    const int niter = K >> 6;

    float acc[2][8][4];
#pragma unroll
    for (int mf = 0; mf < 2; mf++)
#pragma unroll
        for (int nt = 0; nt < 8; nt++)
#pragma unroll
            for (int r = 0; r < 4; r++) acc[mf][nt][r] = 0.f;

    auto issue = [&](int it) {
        if (it >= niter) return;
        int kt = it << 6;
        int st = it % 3;
#pragma unroll
        for (int u = 0; u < 4; u++) {          // A: 128 rows x 64 cols
            int c = tid + 256 * u;
            int r = c >> 3, q = c & 7;
            cp16(sA + (st * A_SZ + r * A_ST + q * 8) * 2,
                 &A[(size_t)(m0 + r) * K + kt + q * 8]);
        }
#pragma unroll
        for (int u = 0; u < 4; u++) {          // B: 64 rows x 128 cols
            int c = tid + 256 * u;
            int r = c >> 4, q = c & 15;
            cp16(sB + (st * B_SZ + r * B_ST + q * 8) * 2,
                 &Bm[(size_t)(kt + r) * Nb + n0 + q * 8]);
        }
    };

    issue(0); CP_COMMIT();
    issue(1); CP_COMMIT();

    for (int i = 0; i < niter; i++) {
        CP_WAIT(1);
        __syncthreads();
        const int st = i % 3;
        const uint32_t ab = sA + st * A_SZ * 2;
        const uint32_t bb = sB + st * B_SZ * 2;
#pragma unroll
        for (int ks = 0; ks < 4; ks++) {
            const int kb = ks * 16;
            uint32_t af[2][4], bf[8][2];
#pragma unroll
            for (int mf = 0; mf < 2; mf++)
                ldmx4(af[mf], ab + ((wm * 32 + mf * 16 + (lane & 15)) * A_ST +
                                    kb + (lane >> 4) * 8) * 2);
#pragma unroll
            for (int p = 0; p < 4; p++) {
                uint32_t r[4];
                ldmx4t(r, bb + ((kb + (lane & 15)) * B_ST +
                                wn * 64 + p * 16 + (lane >> 4) * 8) * 2);
                bf[2 * p][0] = r[0]; bf[2 * p][1] = r[1];
                bf[2 * p + 1][0] = r[2]; bf[2 * p + 1][1] = r[3];
            }
#pragma unroll
            for (int mf = 0; mf < 2; mf++)
#pragma unroll
                for (int nt = 0; nt < 8; nt++)
                    mma_f16(acc[mf][nt], af[mf], bf[nt]);
        }
        issue(i + 2);
        CP_COMMIT();
    }

    // ---------------- epilogue ----------------
    if (mode == 0) {
#pragma unroll
        for (int mf = 0; mf < 2; mf++) {
            int r = m0 + wm * 32 + mf * 16 + g;
#pragma unroll
            for (int nt = 0; nt < 8; nt++) {
                int col = n0 + wn * 64 + nt * 8 + t * 2;
                *(float2*)&C[(size_t)r * DM + col] =
                    make_float2(acc[mf][nt][0], acc[mf][nt][1]);
                *(float2*)&C[(size_t)(r + 8) * DM + col] =
                    make_float2(acc[mf][nt][2], acc[mf][nt][3]);
            }
        }
        return;
    }

#pragma unroll
    for (int mf = 0; mf < 2; mf++) {
#pragma unroll
        for (int hh = 0; hh < 2; hh++) {
            int row = m0 + wm * 32 + mf * 16 + g + hh * 8;
            int b = row >> 11;
            int s = row & (SEQ - 1);
#pragma unroll
            for (int nt = 0; nt < 8; nt++) {
                int col = n0 + wn * 64 + nt * 8 + t * 2;   // even
                float v0 = acc[mf][nt][hh * 2 + 0];
                float v1 = acc[mf][nt][hh * 2 + 1];
                int d0 = col & 63;
                if (vmode != 3) {
                    int j0 = d0 & 31, j1 = (d0 + 1) & 31;
                    float2 cs0 = *(const float2*)&g_rope[((size_t)s * 32 + j0) * 2];
                    float2 cs1 = *(const float2*)&g_rope[((size_t)s * 32 + j1) * 2];
                    float o0 = v0 * cs0.x - v1 * cs0.y;
                    float o1 = v1 * cs1.x + v0 * cs1.y;
                    if (vmode == 1) { o0 *= QSCALE; o1 *= QSCALE; }
                    v0 = o0; v1 = o1;
                }
                int h = col >> 6;
                __half2 hv = __floats2half2_rn(v0, v1);
                if (vmode == 1)
                    *(__half2*)&g_q[(((size_t)b * NUM_HEADS + h) * SEQ + s) * HD + d0] = hv;
                else if (vmode == 2)
                    *(__half2*)&g_k[(((size_t)b * NUM_KV + h) * SEQ + s) * HD + d0] = hv;
                else
                    *(__half2*)&g_v[(((size_t)b * NUM_KV + h) * SEQ + s) * HD + d0] = hv;
            }
        }
    }
}

// ---------------------------------------------------------------------------
// fp16 mma flash attention (unchanged from round 7).
// ---------------------------------------------------------------------------
#define FSTR 72

__global__ __launch_bounds__(256) void fa_f16()
{
    extern __shared__ __half sm[];
    __half* q_s = sm;                        // [128][72]
    __half* k_s = sm + 128 * FSTR;           // [2][64][72]
    __half* v_s = sm + 128 * FSTR + 2 * 64 * FSTR;

    const int tid = threadIdx.x, lane = tid & 31, w = tid >> 5;
    const int g = lane >> 2, t = lane & 3;
    const int qs = ((int)gridDim.x - 1 - (int)blockIdx.x) * 128;  // heavy first
    const int h = blockIdx.y, b = blockIdx.z;
    const int kvh = h >> 2;

    const __half* qg = &g_q[(((size_t)b * NUM_HEADS + h) * SEQ + qs) * HD];
    const __half* kg = &g_k[(((size_t)b * NUM_KV + kvh) * SEQ) * HD];
    const __half* vg = &g_v[(((size_t)b * NUM_KV + kvh) * SEQ) * HD];

    const uint32_t sq = smem_u32(q_s), sk = smem_u32(k_s), sv = smem_u32(v_s);

#pragma unroll
    for (int u = 0; u < 4; u++) {
        int c = tid + 256 * u;
        int r = c >> 3, q = c & 7;
        cp16(sq + (r * FSTR + q * 8) * 2, qg + (size_t)r * 64 + q * 8);
    }
    auto issue_kv = [&](int it) {
        int st = it & 1, koff = it * 64;
#pragma unroll
        for (int u = 0; u < 2; u++) {
            int c = tid + 256 * u;
            int r = c >> 3, q = c & 7;
            cp16(sk + (st * 64 * FSTR + r * FSTR + q * 8) * 2,
                 kg + (size_t)(koff + r) * 64 + q * 8);
            cp16(sv + (st * 64 * FSTR + r * FSTR + q * 8) * 2,
                 vg + (size_t)(koff + r) * 64 + q * 8);
        }
    };
    const int ntiles = qs / 64 + 2;
    issue_kv(0); CP_COMMIT();
    if (ntiles > 1) issue_kv(1);
    CP_COMMIT();

    float o[8][4];
#pragma unroll
    for (int p = 0; p < 8; p++)
#pragma unroll
        for (int r = 0; r < 4; r++) o[p][r] = 0.f;
    float m0r = -1e30f, m1r = -1e30f, l0 = 0.f, l1 = 0.f;
    uint32_t qf[4][4];

    for (int it = 0; it < ntiles; it++) {
        CP_WAIT(1);
        __syncthreads();
        if (it == 0) {
#pragma unroll
            for (int kc = 0; kc < 4; kc++)
                ldmx4(qf[kc], sq + ((w * 16 + (lane & 15)) * FSTR +
                                    kc * 16 + (lane >> 4) * 8) * 2);
        }
        const uint32_t kb = sk + ((it & 1) * 64 * FSTR) * 2;
        const uint32_t vb = sv + ((it & 1) * 64 * FSTR) * 2;

        // S = Q @ K^T (scale pre-folded into Q)
        float s[8][4];
#pragma unroll
        for (int p = 0; p < 8; p++)
#pragma unroll
            for (int r = 0; r < 4; r++) s[p][r] = 0.f;
#pragma unroll
        for (int kc = 0; kc < 4; kc++) {
#pragma unroll
            for (int p = 0; p < 4; p++) {
                uint32_t r[4];
                ldmx4(r, kb + ((p * 16 + (lane & 7) + ((lane >> 4) & 1) * 8) * FSTR +
                               kc * 16 + ((lane >> 3) & 1) * 8) * 2);
                mma_f16(s[2 * p], qf[kc], r);
                mma_f16(s[2 * p + 1], qf[kc], r + 2);
            }
        }

        // causal mask on boundary tiles
        const int kt = it * 64;
        const int rowg = qs + w * 16 + g;
        if (kt + 63 > qs + w * 16) {
#pragma unroll
            for (int p = 0; p < 8; p++) {
                int col = kt + p * 8 + 2 * t;
                if (col > rowg)     s[p][0] = -1e30f;
                if (col + 1 > rowg) s[p][1] = -1e30f;
                if (col > rowg + 8)     s[p][2] = -1e30f;
                if (col + 1 > rowg + 8) s[p][3] = -1e30f;
            }
        }

        // online softmax (rows g and g+8)
        float mx0 = -1e30f, mx1 = -1e30f;
#pragma unroll
        for (int p = 0; p < 8; p++) {
            mx0 = fmaxf(mx0, fmaxf(s[p][0], s[p][1]));
            mx1 = fmaxf(mx1, fmaxf(s[p][2], s[p][3]));
        }
        mx0 = fmaxf(mx0, __shfl_xor_sync(0xffffffffu, mx0, 1));
        mx0 = fmaxf(mx0, __shfl_xor_sync(0xffffffffu, mx0, 2));
        mx1 = fmaxf(mx1, __shfl_xor_sync(0xffffffffu, mx1, 1));
        mx1 = fmaxf(mx1, __shfl_xor_sync(0xffffffffu, mx1, 2));
        float mn0 = fmaxf(m0r, mx0), mn1 = fmaxf(m1r, mx1);
        float a0 = ex2(m0r - mn0), a1 = ex2(m1r - mn1);
        m0r = mn0; m1r = mn1;

        // exp in packed fp16 (same values feed the mma AND the row sum)
        __half2 acc0 = __floats2half2_rn(0.f, 0.f);
        __half2 acc1 = acc0;
        uint32_t pf[4][4];
#pragma unroll
        for (int p = 0; p < 8; p++) {
            uint32_t e0 = ex2h2(packh2(s[p][0] - mn0, s[p][1] - mn0));
            uint32_t e1 = ex2h2(packh2(s[p][2] - mn1, s[p][3] - mn1));
            acc0 = __hadd2(acc0, *reinterpret_cast<__half2*>(&e0));
            acc1 = __hadd2(acc1, *reinterpret_cast<__half2*>(&e1));
            int kc = p >> 1;
            if ((p & 1) == 0) { pf[kc][0] = e0; pf[kc][1] = e1; }
            else              { pf[kc][2] = e0; pf[kc][3] = e1; }
        }
        float ps0 = __low2float(acc0) + __high2float(acc0);
        float ps1 = __low2float(acc1) + __high2float(acc1);
        ps0 += __shfl_xor_sync(0xffffffffu, ps0, 1);
        ps0 += __shfl_xor_sync(0xffffffffu, ps0, 2);
        ps1 += __shfl_xor_sync(0xffffffffu, ps1, 1);
        ps1 += __shfl_xor_sync(0xffffffffu, ps1, 2);
        l0 = l0 * a0 + ps0;
        l1 = l1 * a1 + ps1;
#pragma unroll
        for (int p = 0; p < 8; p++) {
            o[p][0] *= a0; o[p][1] *= a0;
            o[p][2] *= a1; o[p][3] *= a1;
        }

        // O += P @ V
#pragma unroll
        for (int kc = 0; kc < 4; kc++) {
#pragma unroll
            for (int p = 0; p < 4; p++) {
                uint32_t r[4];
                ldmx4t(r, vb + ((kc * 16 + (lane & 15)) * FSTR +
                                p * 16 + ((lane >> 4) & 1) * 8) * 2);
                mma_f16(o[2 * p], pf[kc], r);
                mma_f16(o[2 * p + 1], pf[kc], r + 2);
            }
        }

        __syncthreads();
        if (it + 2 < ntiles) issue_kv(it + 2);
        CP_COMMIT();
    }

    // epilogue
    float inv0 = 1.f / l0, inv1 = 1.f / l1;
    __half* og = &g_ao[((size_t)(b * SEQ + qs + w * 16)) * DM + h * HD];
#pragma unroll
    for (int p = 0; p < 8; p++) {
        int col = p * 8 + 2 * t;
        *(__half2*)&og[(size_t)g * DM + col] =
            __floats2half2_rn(o[p][0] * inv0, o[p][1] * inv0);
        *(__half2*)&og[(size_t)(g + 8) * DM + col] =
            __floats2half2_rn(o[p][2] * inv1, o[p][3] * inv1);
    }
}

// ---------------------------------------------------------------------------

extern "C" void kernel_launch(void* const* d_in, const int* in_sizes, int n_in,
                              void* d_out, int out_size)
{
    const float* x  = (const float*)d_in[0];
    const float* Wq = (const float*)d_in[2];
    const float* Wk = (const float*)d_in[3];
    const float* Wv = (const float*)d_in[4];
    const float* Wo = (const float*)d_in[5];
    float* out = (float*)d_out;

    void *xh, *wq, *wk, *wv, *wo, *ao;
    cudaGetSymbolAddress(&xh, g_xh);
    cudaGetSymbolAddress(&wq, g_wq);
    cudaGetSymbolAddress(&wk, g_wk);
    cudaGetSymbolAddress(&wv, g_wv);
    cudaGetSymbolAddress(&wo, g_wo);
    cudaGetSymbolAddress(&ao, g_ao);

    cudaFuncSetAttribute(gemm_f16, cudaFuncAttributeMaxDynamicSharedMemorySize, GSMEM);
    cudaFuncSetAttribute(fa_f16, cudaFuncAttributeMaxDynamicSharedMemorySize,
                         (128 + 4 * 64) * FSTR * 2);

    // fused prologue: all conversions + rope table (one launch)
    prep<<<18688, 256>>>((const float4*)x, (const float4*)Wq, (const float4*)Wk,
                         (const float4*)Wv, (const float4*)Wo);

    // fused Q+K+V projections (RoPE on Q/K, scale folded into Q)
    gemm_f16<<<dim3(24, MTOT / 128), 256, GSMEM>>>(
        (const __half*)xh, (const __half*)wq, (const __half*)wk,
        (const __half*)wv, nullptr, DM, 4);

    // flash attention (heavy-first)
    fa_f16<<<dim3(SEQ / 128, NUM_HEADS, B_DIM), 256, (128 + 4 * 64) * FSTR * 2>>>();

    // output projection
    gemm_f16<<<dim3(DM / 128, MTOT / 128), 256, GSMEM>>>(
        (const __half*)ao, (const __half*)wo, nullptr, nullptr, out, DM, 0);
}

// round 9
// speedup vs baseline: 4.7518x; 1.0084x over previous
#include <cuda_runtime.h>
#include <cuda_fp16.h>
#include <math.h>
#include <stdint.h>

#define B_DIM 2
#define NUM_HEADS 32
#define NUM_KV 8
#define SEQ 2048
#define DM 2048
#define HD 64
#define MTOT (B_DIM * SEQ)

// fp16 scratch (allocation-free device globals)
__device__ __half g_xh[(size_t)MTOT * DM];
__device__ __half g_wq[(size_t)DM * DM];
__device__ __half g_wk[(size_t)DM * 512];
__device__ __half g_wv[(size_t)DM * 512];
__device__ __half g_wo[(size_t)DM * DM];
__device__ __half g_q[(size_t)B_DIM * NUM_HEADS * SEQ * HD];
__device__ __half g_k[(size_t)B_DIM * NUM_KV * SEQ * HD];
__device__ __half g_v[(size_t)B_DIM * NUM_KV * SEQ * HD];
__device__ __half g_ao[(size_t)MTOT * DM];
__device__ float  g_rope[SEQ * 32 * 2];

// softmax scale folded into Q at projection time: 1/sqrt(64) * log2(e)
#define QSCALE 0.1803368801111204f

// ---------------------------------------------------------------------------
// Fused prologue: all fp32->fp16 conversions + RoPE table in ONE launch.
// ---------------------------------------------------------------------------
__global__ void prep(const float4* __restrict__ x, const float4* __restrict__ wq,
                     const float4* __restrict__ wk, const float4* __restrict__ wv,
                     const float4* __restrict__ wo)
{
    const int b = blockIdx.x, tid = threadIdx.x;
    const float4* src;
    __half* dst;
    int base;
    if (b < 8192)       { src = x;  dst = g_xh; base = 0; }
    else if (b < 12288) { src = wq; dst = g_wq; base = 8192; }
    else if (b < 13312) { src = wk; dst = g_wk; base = 12288; }
    else if (b < 14336) { src = wv; dst = g_wv; base = 13312; }
    else if (b < 18432) { src = wo; dst = g_wo; base = 14336; }
    else {
        int i = (b - 18432) * 256 + tid;
        int s = i >> 5, j = i & 31;
        float inv = expf(-(float)j * 0.28782313662425572f);
        float sv, cv;
        sincosf((float)s * inv, &sv, &cv);
        g_rope[(size_t)i * 2 + 0] = cv;
        g_rope[(size_t)i * 2 + 1] = sv;
        return;
    }
    size_t i = (size_t)(b - base) * 256 + tid;
    float4 v = src[i];
    __half2* d = (__half2*)(dst + i * 4);
    d[0] = __floats2half2_rn(v.x, v.y);
    d[1] = __floats2half2_rn(v.z, v.w);
}

// ---------------------------------------------------------------------------
// Helpers
// ---------------------------------------------------------------------------
__device__ __forceinline__ uint32_t smem_u32(const void* p)
{
    return (uint32_t)__cvta_generic_to_shared(p);
}
__device__ __forceinline__ void ldmx4(uint32_t* r, uint32_t a)
{
    asm volatile("ldmatrix.sync.aligned.m8n8.x4.shared.b16 {%0,%1,%2,%3}, [%4];"
                 : "=r"(r[0]), "=r"(r[1]), "=r"(r[2]), "=r"(r[3]) : "r"(a));
}
__device__ __forceinline__ void ldmx4t(uint32_t* r, uint32_t a)
{
    asm volatile("ldmatrix.sync.aligned.m8n8.x4.trans.shared.b16 {%0,%1,%2,%3}, [%4];"
                 : "=r"(r[0]), "=r"(r[1]), "=r"(r[2]), "=r"(r[3]) : "r"(a));
}
__device__ __forceinline__ void mma_f16(float* c, const uint32_t* a, const uint32_t* b)
{
    asm volatile(
        "mma.sync.aligned.m16n8k16.row.col.f32.f16.f16.f32 "
        "{%0,%1,%2,%3}, {%4,%5,%6,%7}, {%8,%9}, {%0,%1,%2,%3};"
        : "+f"(c[0]), "+f"(c[1]), "+f"(c[2]), "+f"(c[3])
        : "r"(a[0]), "r"(a[1]), "r"(a[2]), "r"(a[3]), "r"(b[0]), "r"(b[1]));
}
__device__ __forceinline__ void cp16(uint32_t saddr, const void* g)
{
    asm volatile("cp.async.cg.shared.global [%0], [%1], 16;" :: "r"(saddr), "l"(g));
}
#define CP_COMMIT() asm volatile("cp.async.commit_group;")
#define CP_WAIT(n)  asm volatile("cp.async.wait_group %0;" :: "n"(n))

__device__ __forceinline__ float ex2(float x)
{
    float r;
    asm("ex2.approx.ftz.f32 %0, %1;" : "=f"(r) : "f"(x));
    return r;
}
__device__ __forceinline__ uint32_t ex2h2(uint32_t x)
{
    uint32_t r;
    asm("ex2.approx.f16x2 %0, %1;" : "=r"(r) : "r"(x));
    return r;
}
__device__ __forceinline__ uint32_t packh2(float lo, float hi)
{
    __half2 h = __floats2half2_rn(lo, hi);
    return *reinterpret_cast<uint32_t*>(&h);
}

// ---------------------------------------------------------------------------
// fp16 GEMM, CTA 128x128, BK=64, 8 warps (4m x 2n, warp tile 32x64),
// 3-stage cp.async pipeline, 2 CTAs/SM.  (unchanged from round 8)
// ---------------------------------------------------------------------------
#define A_ST 72
#define B_ST 136
#define A_SZ (128 * A_ST)
#define B_SZ (64 * B_ST)
#define GSMEM (3 * (A_SZ + B_SZ) * 2)

__global__ __launch_bounds__(256, 2) void gemm_f16(
    const __half* __restrict__ A, const __half* __restrict__ B0,
    const __half* __restrict__ B1, const __half* __restrict__ B2,
    float* __restrict__ C, int K, int mode)
{
    extern __shared__ __half smem[];
    __half* As = smem;
    __half* Bs = smem + 3 * A_SZ;

    const int tid = threadIdx.x, lane = tid & 31, wid = tid >> 5;
    const int wm = wid & 3, wn = wid >> 2;
    const int g = lane >> 2, t = lane & 3;
    const int m0 = blockIdx.y * 128;
    int n0 = blockIdx.x * 128;
    const __half* Bm = B0;
    int Nb = DM;
    int vmode = mode;
    if (mode == 4) {
        if (blockIdx.x < 16) {
            vmode = 1;
        } else if (blockIdx.x < 20) {
            Bm = B1; Nb = 512; n0 = (blockIdx.x - 16) * 128; vmode = 2;
        } else {
            Bm = B2; Nb = 512; n0 = (blockIdx.x - 20) * 128; vmode = 3;
        }
    }

    const uint32_t sA = smem_u32(As), sB = smem_u32(Bs);
    const int niter = K >> 6;

    float acc[2][8][4];
#pragma unroll
    for (int mf = 0; mf < 2; mf++)
#pragma unroll
        for (int nt = 0; nt < 8; nt++)
#pragma unroll
            for (int r = 0; r < 4; r++) acc[mf][nt][r] = 0.f;

    auto issue = [&](int it) {
        if (it >= niter) return;
        int kt = it << 6;
        int st = it % 3;
#pragma unroll
        for (int u = 0; u < 4; u++) {
            int c = tid + 256 * u;
            int r = c >> 3, q = c & 7;
            cp16(sA + (st * A_SZ + r * A_ST + q * 8) * 2,
                 &A[(size_t)(m0 + r) * K + kt + q * 8]);
        }
#pragma unroll
        for (int u = 0; u < 4; u++) {
            int c = tid + 256 * u;
            int r = c >> 4, q = c & 15;
            cp16(sB + (st * B_SZ + r * B_ST + q * 8) * 2,
                 &Bm[(size_t)(kt + r) * Nb + n0 + q * 8]);
        }
    };

    issue(0); CP_COMMIT();
    issue(1); CP_COMMIT();

    for (int i = 0; i < niter; i++) {
        CP_WAIT(1);
        __syncthreads();
        const int st = i % 3;
        const uint32_t ab = sA + st * A_SZ * 2;
        const uint32_t bb = sB + st * B_SZ * 2;
#pragma unroll
        for (int ks = 0; ks < 4; ks++) {
            const int kb = ks * 16;
            uint32_t af[2][4], bf[8][2];
#pragma unroll
            for (int mf = 0; mf < 2; mf++)
                ldmx4(af[mf], ab + ((wm * 32 + mf * 16 + (lane & 15)) * A_ST +
                                    kb + (lane >> 4) * 8) * 2);
#pragma unroll
            for (int p = 0; p < 4; p++) {
                uint32_t r[4];
                ldmx4t(r, bb + ((kb + (lane & 15)) * B_ST +
                                wn * 64 + p * 16 + (lane >> 4) * 8) * 2);
                bf[2 * p][0] = r[0]; bf[2 * p][1] = r[1];
                bf[2 * p + 1][0] = r[2]; bf[2 * p + 1][1] = r[3];
            }
#pragma unroll
            for (int mf = 0; mf < 2; mf++)
#pragma unroll
                for (int nt = 0; nt < 8; nt++)
                    mma_f16(acc[mf][nt], af[mf], bf[nt]);
        }
        issue(i + 2);
        CP_COMMIT();
    }

    if (mode == 0) {
#pragma unroll
        for (int mf = 0; mf < 2; mf++) {
            int r = m0 + wm * 32 + mf * 16 + g;
#pragma unroll
            for (int nt = 0; nt < 8; nt++) {
                int col = n0 + wn * 64 + nt * 8 + t * 2;
                *(float2*)&C[(size_t)r * DM + col] =
                    make_float2(acc[mf][nt][0], acc[mf][nt][1]);
                *(float2*)&C[(size_t)(r + 8) * DM + col] =
                    make_float2(acc[mf][nt][2], acc[mf][nt][3]);
            }
        }
        return;
    }

#pragma unroll
    for (int mf = 0; mf < 2; mf++) {
#pragma unroll
        for (int hh = 0; hh < 2; hh++) {
            int row = m0 + wm * 32 + mf * 16 + g + hh * 8;
            int b = row >> 11;
            int s = row & (SEQ - 1);
#pragma unroll
            for (int nt = 0; nt < 8; nt++) {
                int col = n0 + wn * 64 + nt * 8 + t * 2;
                float v0 = acc[mf][nt][hh * 2 + 0];
                float v1 = acc[mf][nt][hh * 2 + 1];
                int d0 = col & 63;
                if (vmode != 3) {
                    int j0 = d0 & 31, j1 = (d0 + 1) & 31;
                    float2 cs0 = *(const float2*)&g_rope[((size_t)s * 32 + j0) * 2];
                    float2 cs1 = *(const float2*)&g_rope[((size_t)s * 32 + j1) * 2];
                    float o0 = v0 * cs0.x - v1 * cs0.y;
                    float o1 = v1 * cs1.x + v0 * cs1.y;
                    if (vmode == 1) { o0 *= QSCALE; o1 *= QSCALE; }
                    v0 = o0; v1 = o1;
                }
                int h = col >> 6;
                __half2 hv = __floats2half2_rn(v0, v1);
                if (vmode == 1)
                    *(__half2*)&g_q[(((size_t)b * NUM_HEADS + h) * SEQ + s) * HD + d0] = hv;
                else if (vmode == 2)
                    *(__half2*)&g_k[(((size_t)b * NUM_KV + h) * SEQ + s) * HD + d0] = hv;
                else
                    *(__half2*)&g_v[(((size_t)b * NUM_KV + h) * SEQ + s) * HD + d0] = hv;
            }
        }
    }
}

// ---------------------------------------------------------------------------
// fp16 mma flash attention v2: 128 threads (4 warps), each warp owns 32 Q rows
// x full 64-wide KV tile -> 128 HMMA per 32 LDSM per warp per tile (was 1:1).
// K-fragments shared across the two 16-row halves. 2 CTAs/SM.
// ---------------------------------------------------------------------------
#define FSTR 72
#define FA_SMEM ((128 + 4 * 64) * FSTR * 2)

__global__ __launch_bounds__(128) void fa_f16()
{
    extern __shared__ __half sm[];
    __half* q_s = sm;                        // [128][72]
    __half* k_s = sm + 128 * FSTR;           // [2][64][72]
    __half* v_s = sm + 128 * FSTR + 2 * 64 * FSTR;

    const int tid = threadIdx.x, lane = tid & 31, w = tid >> 5;   // w: 0..3
    const int g = lane >> 2, t = lane & 3;
    const int qs = ((int)gridDim.x - 1 - (int)blockIdx.x) * 128;  // heavy first
    const int h = blockIdx.y, b = blockIdx.z;
    const int kvh = h >> 2;

    const __half* qg = &g_q[(((size_t)b * NUM_HEADS + h) * SEQ + qs) * HD];
    const __half* kg = &g_k[(((size_t)b * NUM_KV + kvh) * SEQ) * HD];
    const __half* vg = &g_v[(((size_t)b * NUM_KV + kvh) * SEQ) * HD];

    const uint32_t sq = smem_u32(q_s), sk = smem_u32(k_s), sv = smem_u32(v_s);

    // Q tile: 128 rows x 64 cols, 8 cp16 per thread
#pragma unroll
    for (int u = 0; u < 8; u++) {
        int c = tid + 128 * u;
        int r = c >> 3, q = c & 7;
        cp16(sq + (r * FSTR + q * 8) * 2, qg + (size_t)r * 64 + q * 8);
    }
    auto issue_kv = [&](int it) {
        int st = it & 1, koff = it * 64;
#pragma unroll
        for (int u = 0; u < 4; u++) {
            int c = tid + 128 * u;
            int r = c >> 3, q = c & 7;
            cp16(sk + (st * 64 * FSTR + r * FSTR + q * 8) * 2,
                 kg + (size_t)(koff + r) * 64 + q * 8);
            cp16(sv + (st * 64 * FSTR + r * FSTR + q * 8) * 2,
                 vg + (size_t)(koff + r) * 64 + q * 8);
        }
    };
    const int ntiles = qs / 64 + 2;
    issue_kv(0); CP_COMMIT();
    if (ntiles > 1) issue_kv(1);
    CP_COMMIT();

    // per-warp state: 32 Q rows (two 16-row halves mf=0,1)
    float o[2][8][4];
#pragma unroll
    for (int mf = 0; mf < 2; mf++)
#pragma unroll
        for (int p = 0; p < 8; p++)
#pragma unroll
            for (int r = 0; r < 4; r++) o[mf][p][r] = 0.f;
    float mr[2][2], lr[2][2];
#pragma unroll
    for (int mf = 0; mf < 2; mf++) {
        mr[mf][0] = mr[mf][1] = -1e30f;
        lr[mf][0] = lr[mf][1] = 0.f;
    }
    uint32_t qf[2][4][4];

    for (int it = 0; it < ntiles; it++) {
        CP_WAIT(1);
        __syncthreads();
        if (it == 0) {
#pragma unroll
            for (int mf = 0; mf < 2; mf++)
#pragma unroll
                for (int kc = 0; kc < 4; kc++)
                    ldmx4(qf[mf][kc],
                          sq + ((w * 32 + mf * 16 + (lane & 15)) * FSTR +
                                kc * 16 + (lane >> 4) * 8) * 2);
        }
        const uint32_t kb = sk + ((it & 1) * 64 * FSTR) * 2;
        const uint32_t vb = sv + ((it & 1) * 64 * FSTR) * 2;

        // S = Q @ K^T : K-frags loaded once, used by both m-halves
        float s[2][8][4];
#pragma unroll
        for (int mf = 0; mf < 2; mf++)
#pragma unroll
            for (int p = 0; p < 8; p++)
#pragma unroll
                for (int r = 0; r < 4; r++) s[mf][p][r] = 0.f;
#pragma unroll
        for (int kc = 0; kc < 4; kc++) {
#pragma unroll
            for (int p = 0; p < 4; p++) {
                uint32_t r[4];
                ldmx4(r, kb + ((p * 16 + (lane & 7) + ((lane >> 4) & 1) * 8) * FSTR +
                               kc * 16 + ((lane >> 3) & 1) * 8) * 2);
#pragma unroll
                for (int mf = 0; mf < 2; mf++) {
                    mma_f16(s[mf][2 * p], qf[mf][kc], r);
                    mma_f16(s[mf][2 * p + 1], qf[mf][kc], r + 2);
                }
            }
        }

        // causal mask + online softmax per m-half
        const int kt = it * 64;
        uint32_t pf[2][4][4];
#pragma unroll
        for (int mf = 0; mf < 2; mf++) {
            const int rowg = qs + w * 32 + mf * 16 + g;
            if (kt + 63 > qs + w * 32 + mf * 16) {
#pragma unroll
                for (int p = 0; p < 8; p++) {
                    int col = kt + p * 8 + 2 * t;
                    if (col > rowg)     s[mf][p][0] = -1e30f;
                    if (col + 1 > rowg) s[mf][p][1] = -1e30f;
                    if (col > rowg + 8)     s[mf][p][2] = -1e30f;
                    if (col + 1 > rowg + 8) s[mf][p][3] = -1e30f;
                }
            }

            float mx0 = -1e30f, mx1 = -1e30f;
#pragma unroll
            for (int p = 0; p < 8; p++) {
                mx0 = fmaxf(mx0, fmaxf(s[mf][p][0], s[mf][p][1]));
                mx1 = fmaxf(mx1, fmaxf(s[mf][p][2], s[mf][p][3]));
            }
            mx0 = fmaxf(mx0, __shfl_xor_sync(0xffffffffu, mx0, 1));
            mx0 = fmaxf(mx0, __shfl_xor_sync(0xffffffffu, mx0, 2));
            mx1 = fmaxf(mx1, __shfl_xor_sync(0xffffffffu, mx1, 1));
            mx1 = fmaxf(mx1, __shfl_xor_sync(0xffffffffu, mx1, 2));
            float mn0 = fmaxf(mr[mf][0], mx0), mn1 = fmaxf(mr[mf][1], mx1);
            float a0 = ex2(mr[mf][0] - mn0), a1 = ex2(mr[mf][1] - mn1);
            mr[mf][0] = mn0; mr[mf][1] = mn1;

            __half2 acc0 = __floats2half2_rn(0.f, 0.f);
            __half2 acc1 = acc0;
#pragma unroll
            for (int p = 0; p < 8; p++) {
                uint32_t e0 = ex2h2(packh2(s[mf][p][0] - mn0, s[mf][p][1] - mn0));
                uint32_t e1 = ex2h2(packh2(s[mf][p][2] - mn1, s[mf][p][3] - mn1));
                acc0 = __hadd2(acc0, *reinterpret_cast<__half2*>(&e0));
                acc1 = __hadd2(acc1, *reinterpret_cast<__half2*>(&e1));
                int kc = p >> 1;
                if ((p & 1) == 0) { pf[mf][kc][0] = e0; pf[mf][kc][1] = e1; }
                else              { pf[mf][kc][2] = e0; pf[mf][kc][3] = e1; }
            }
            float ps0 = __low2float(acc0) + __high2float(acc0);
            float ps1 = __low2float(acc1) + __high2float(acc1);
            ps0 += __shfl_xor_sync(0xffffffffu, ps0, 1);
            ps0 += __shfl_xor_sync(0xffffffffu, ps0, 2);
            ps1 += __shfl_xor_sync(0xffffffffu, ps1, 1);
            ps1 += __shfl_xor_sync(0xffffffffu, ps1, 2);
            lr[mf][0] = lr[mf][0] * a0 + ps0;
            lr[mf][1] = lr[mf][1] * a1 + ps1;
#pragma unroll
            for (int p = 0; p < 8; p++) {
                o[mf][p][0] *= a0; o[mf][p][1] *= a0;
                o[mf][p][2] *= a1; o[mf][p][3] *= a1;
            }
        }

        // O += P @ V : V-frags loaded once, used by both m-halves
#pragma unroll
        for (int kc = 0; kc < 4; kc++) {
#pragma unroll
            for (int p = 0; p < 4; p++) {
                uint32_t r[4];
                ldmx4t(r, vb + ((kc * 16 + (lane & 15)) * FSTR +
                                p * 16 + ((lane >> 4) & 1) * 8) * 2);
#pragma unroll
                for (int mf = 0; mf < 2; mf++) {
                    mma_f16(o[mf][2 * p], pf[mf][kc], r);
                    mma_f16(o[mf][2 * p + 1], pf[mf][kc], r + 2);
                }
            }
        }

        __syncthreads();
        if (it + 2 < ntiles) issue_kv(it + 2);
        CP_COMMIT();
    }

    // epilogue
#pragma unroll
    for (int mf = 0; mf < 2; mf++) {
        float inv0 = 1.f / lr[mf][0], inv1 = 1.f / lr[mf][1];
        __half* og = &g_ao[((size_t)(b * SEQ + qs + w * 32 + mf * 16)) * DM + h * HD];
#pragma unroll
        for (int p = 0; p < 8; p++) {
            int col = p * 8 + 2 * t;
            *(__half2*)&og[(size_t)g * DM + col] =
                __floats2half2_rn(o[mf][p][0] * inv0, o[mf][p][1] * inv0);
            *(__half2*)&og[(size_t)(g + 8) * DM + col] =
                __floats2half2_rn(o[mf][p][2] * inv1, o[mf][p][3] * inv1);
        }
    }
}

// ---------------------------------------------------------------------------

extern "C" void kernel_launch(void* const* d_in, const int* in_sizes, int n_in,
                              void* d_out, int out_size)
{
    const float* x  = (const float*)d_in[0];
    const float* Wq = (const float*)d_in[2];
    const float* Wk = (const float*)d_in[3];
    const float* Wv = (const float*)d_in[4];
    const float* Wo = (const float*)d_in[5];
    float* out = (float*)d_out;

    void *xh, *wq, *wk, *wv, *wo, *ao;
    cudaGetSymbolAddress(&xh, g_xh);
    cudaGetSymbolAddress(&wq, g_wq);
    cudaGetSymbolAddress(&wk, g_wk);
    cudaGetSymbolAddress(&wv, g_wv);
    cudaGetSymbolAddress(&wo, g_wo);
    cudaGetSymbolAddress(&ao, g_ao);

    cudaFuncSetAttribute(gemm_f16, cudaFuncAttributeMaxDynamicSharedMemorySize, GSMEM);
    cudaFuncSetAttribute(fa_f16, cudaFuncAttributeMaxDynamicSharedMemorySize, FA_SMEM);

    // fused prologue: all conversions + rope table (one launch)
    prep<<<18688, 256>>>((const float4*)x, (const float4*)Wq, (const float4*)Wk,
                         (const float4*)Wv, (const float4*)Wo);

    // fused Q+K+V projections (RoPE on Q/K, scale folded into Q)
    gemm_f16<<<dim3(24, MTOT / 128), 256, GSMEM>>>(
        (const __half*)xh, (const __half*)wq, (const __half*)wk,
        (const __half*)wv, nullptr, DM, 4);

    // flash attention (4 warps x 32 rows, heavy-first)
    fa_f16<<<dim3(SEQ / 128, NUM_HEADS, B_DIM), 128, FA_SMEM>>>();

    // output projection
    gemm_f16<<<dim3(DM / 128, MTOT / 128), 256, GSMEM>>>(
        (const __half*)ao, (const __half*)wo, nullptr, nullptr, out, DM, 0);
}